// round 10
// baseline (speedup 1.0000x reference)
#include <cuda_runtime.h>

#define NFFT 16000
#define NH   8000
#define BT   800
// 16000-domain padding (forward stages)
#define PHI(i)  ((i) + 6 * ((i) / 100))
#define SMPAD   (NFFT + 6 * (NFFT / 100))        // 16960 float2
// 8000-domain padding (inverse stages), separate region
#define PHI8(i) ((i) + 3 * ((i) / 50))
#define SMPAD8  (NH + 3 * (NH / 50))             // 8480 float2
#define SMTOTAL ((SMPAD + SMPAD8) * sizeof(float2))  // 203,520 B

// Forward plan (DIF) on 16000: 16,10,10,10 -> strides 1000,100,10,1
// Inverse plan (DIT) on 8000:  [16,10,10,5]; digit maps as in earlier rounds.

__device__ __align__(16) float2 g_tw[NFFT];       // e^{-2*pi*i*t/16000}
// (w1, w2) pair tables, indexed by n2 (lane-coalesced); inverse pre-conjugated
__device__ __align__(16) float4 g_twp16[1000];    // fwd16:  (g_tw[n2],     g_tw[2*n2])
__device__ __align__(16) float4 g_twpf1000[100];  // fwd10a: (g_tw[16*n2],  g_tw[32*n2])
__device__ __align__(16) float4 g_twpf100[10];    // fwd10b: (g_tw[160*n2], g_tw[320*n2])
__device__ __align__(16) float4 g_twpi50[5];      // inv10a: conj(g_tw[320*n2], g_tw[640*n2])
__device__ __align__(16) float4 g_twpi500[50];    // inv10b: conj(g_tw[32*n2],  g_tw[64*n2])
__device__ __align__(16) float4 g_twpi8000[500];  // inv16:  conj(g_tw[2*n2],   g_tw[4*n2])

__device__ __forceinline__ float4 tw_pair(double k, double sgn) {
    const double TWO_PI = 6.283185307179586476925286766559;
    double a1 = sgn * TWO_PI * k / (double)NFFT;
    double a2 = sgn * TWO_PI * (2.0 * k) / (double)NFFT;
    return make_float4((float)cos(a1), (float)sin(a1), (float)cos(a2), (float)sin(a2));
}

__global__ void init_tables_kernel() {
    int p = blockIdx.x * blockDim.x + threadIdx.x;
    if (p < NFFT) {
        double ang = -6.283185307179586476925286766559 * (double)p / (double)NFFT;
        g_tw[p] = make_float2((float)cos(ang), (float)sin(ang));
    }
    if (p < 1000) g_twp16[p]    = tw_pair((double)p,          -1.0);
    if (p < 100)  g_twpf1000[p] = tw_pair((double)(16 * p),   -1.0);
    if (p < 10)   g_twpf100[p]  = tw_pair((double)(160 * p),  -1.0);
    if (p < 5)    g_twpi50[p]   = tw_pair((double)(320 * p),   1.0);
    if (p < 50)   g_twpi500[p]  = tw_pair((double)(32 * p),    1.0);
    if (p < 500)  g_twpi8000[p] = tw_pair((double)(2 * p),     1.0);
}

__device__ __forceinline__ int block_of(int f0) {
    return 100 * (f0 & 15) + 10 * ((f0 >> 4) % 10) + (f0 / 160);
}

__device__ __forceinline__ float2 cadd(float2 a, float2 b) { return make_float2(a.x + b.x, a.y + b.y); }
__device__ __forceinline__ float2 csub(float2 a, float2 b) { return make_float2(a.x - b.x, a.y - b.y); }
__device__ __forceinline__ float2 cmul(float2 a, float2 b) {
    return make_float2(fmaf(a.x, b.x, -a.y * b.y), fmaf(a.x, b.y, a.y * b.x));
}
__device__ __forceinline__ float2 cmulc(float2 a, float cr, float ci) {
    return make_float2(fmaf(a.x, cr, -a.y * ci), fmaf(a.x, ci, a.y * cr));
}
template <int DIR>
__device__ __forceinline__ float2 cmuli(float2 a) {   // * (DIR*i)
    return (DIR > 0) ? make_float2(-a.y, a.x) : make_float2(a.y, -a.x);
}

template <int DIR>
__device__ __forceinline__ void dft4(float2* x) {
    float2 t0 = cadd(x[0], x[2]);
    float2 t1 = csub(x[0], x[2]);
    float2 t2 = cadd(x[1], x[3]);
    float2 t3 = cmuli<DIR>(csub(x[1], x[3]));
    x[0] = cadd(t0, t2);
    x[2] = csub(t0, t2);
    x[1] = cadd(t1, t3);
    x[3] = csub(t1, t3);
}

template <int DIR>
__device__ __forceinline__ void dft5(float2* x) {
    const float c1 = 0.30901699437494742f;
    const float c2 = -0.80901699437494745f;
    const float s1 = 0.95105651629515357f;
    const float s2 = 0.58778525229247313f;
    float2 t1 = cadd(x[1], x[4]);
    float2 t2 = cadd(x[2], x[3]);
    float2 t3 = csub(x[1], x[4]);
    float2 t4 = csub(x[2], x[3]);
    float2 x0 = x[0];
    float2 a1 = make_float2(x0.x + c1 * t1.x + c2 * t2.x, x0.y + c1 * t1.y + c2 * t2.y);
    float2 a2 = make_float2(x0.x + c2 * t1.x + c1 * t2.x, x0.y + c2 * t1.y + c1 * t2.y);
    float2 b1 = make_float2(s1 * t3.x + s2 * t4.x, s1 * t3.y + s2 * t4.y);
    float2 b2 = make_float2(s2 * t3.x - s1 * t4.x, s2 * t3.y - s1 * t4.y);
    x[0] = make_float2(x0.x + t1.x + t2.x, x0.y + t1.y + t2.y);
    float2 ib1 = cmuli<DIR>(b1);
    float2 ib2 = cmuli<DIR>(b2);
    x[1] = cadd(a1, ib1);
    x[4] = csub(a1, ib1);
    x[2] = cadd(a2, ib2);
    x[3] = csub(a2, ib2);
}

// 10-point DFT = 2x5 CT, stride-S register access.
template <int DIR, int S>
__device__ __forceinline__ void dft10s(float2* x) {
    const float C36 = 0.80901699437494742f;
    const float S36 = 0.58778525229247313f;
    const float C72 = 0.30901699437494742f;
    const float S72 = 0.95105651629515357f;
    const float D = (float)DIR;
    float2 a[5], c[5];
#pragma unroll
    for (int k = 0; k < 5; k++) {
        a[k] = cadd(x[k * S], x[(k + 5) * S]);
        c[k] = csub(x[k * S], x[(k + 5) * S]);
    }
    c[1] = cmulc(c[1], C36, D * S36);
    c[2] = cmulc(c[2], C72, D * S72);
    c[3] = cmulc(c[3], -C72, D * S72);
    c[4] = cmulc(c[4], -C36, D * S36);
    dft5<DIR>(a);
    dft5<DIR>(c);
    x[0 * S] = a[0]; x[2 * S] = a[1]; x[4 * S] = a[2]; x[6 * S] = a[3]; x[8 * S] = a[4];
    x[1 * S] = c[0]; x[3 * S] = c[1]; x[5 * S] = c[2]; x[7 * S] = c[3]; x[9 * S] = c[4];
}

// 16-point DFT = 4x4 CT, stride-S register access.
template <int DIR, int S>
__device__ __forceinline__ void dft16s(float2* x) {
    const float C1 = 0.92387953251128674f;
    const float S1 = 0.38268343236508978f;
    const float C2 = 0.70710678118654752f;
    const float D = (float)DIR;
    float2 y[16];
#pragma unroll
    for (int n2 = 0; n2 < 4; n2++) {
        float2 t[4] = {x[n2 * S], x[(n2 + 4) * S], x[(n2 + 8) * S], x[(n2 + 12) * S]};
        dft4<DIR>(t);
        if (n2 == 1) {
            t[1] = cmulc(t[1], C1, D * S1);
            t[2] = cmulc(t[2], C2, D * C2);
            t[3] = cmulc(t[3], S1, D * C1);
        } else if (n2 == 2) {
            t[1] = cmulc(t[1], C2, D * C2);
            t[2] = cmuli<DIR>(t[2]);
            t[3] = cmulc(t[3], -C2, D * C2);
        } else if (n2 == 3) {
            t[1] = cmulc(t[1], S1, D * C1);
            t[2] = cmulc(t[2], -C2, D * C2);
            t[3] = cmulc(t[3], -C1, -D * S1);
        }
        y[0 + n2] = t[0]; y[4 + n2] = t[1]; y[8 + n2] = t[2]; y[12 + n2] = t[3];
    }
#pragma unroll
    for (int k1 = 0; k1 < 4; k1++) {
        float2 t[4] = {y[k1 * 4 + 0], y[k1 * 4 + 1], y[k1 * 4 + 2], y[k1 * 4 + 3]};
        dft4<DIR>(t);
        x[(k1 + 0) * S] = t[0]; x[(k1 + 4) * S] = t[1];
        x[(k1 + 8) * S] = t[2]; x[(k1 + 12) * S] = t[3];
    }
}

// ---- twiddle application; (w1, w2) supplied from tables ----

// radix-10: 4-chain tree, 7 cmuls, depth 3.
template <int S>
__device__ __forceinline__ void apply_tw10_pc(float2* x, float2 w1, float2 w2) {
    float2 w3 = cmul(w1, w2);
    float2 w4 = cmul(w2, w2);
    x[1 * S] = cmul(x[1 * S], w1);
    x[2 * S] = cmul(x[2 * S], w2);
    x[3 * S] = cmul(x[3 * S], w3);
    x[4 * S] = cmul(x[4 * S], w4);
    float2 w5 = cmul(w1, w4);
    float2 w6 = cmul(w2, w4);
    float2 w7 = cmul(w3, w4);
    float2 w8 = cmul(w4, w4);
    x[5 * S] = cmul(x[5 * S], w5);
    x[6 * S] = cmul(x[6 * S], w6);
    x[7 * S] = cmul(x[7 * S], w7);
    x[8 * S] = cmul(x[8 * S], w8);
    x[9 * S] = cmul(x[9 * S], cmul(w5, w4));
}

// radix-16, register-lean 2-chain form (for fwd16 where X[32] is live): depth 7.
template <int S>
__device__ __forceinline__ void apply_tw16_chain(float2* x, float2 w1, float2 w2) {
    float2 wo = w1, we = w2;
    x[1 * S] = cmul(x[1 * S], wo);
    x[2 * S] = cmul(x[2 * S], we);
#pragma unroll
    for (int j = 3; j < 16; j += 2) {
        wo = cmul(wo, w2); x[j * S] = cmul(x[j * S], wo);
        if (j + 1 < 16) { we = cmul(we, w2); x[(j + 1) * S] = cmul(x[(j + 1) * S], we); }
    }
}

// radix-16, 4-chain tree (for inv16 where only x[16] is live): 13 cmuls, depth 4.
template <int S>
__device__ __forceinline__ void apply_tw16_tree(float2* x, float2 w1, float2 w2) {
    float2 w3 = cmul(w1, w2);
    float2 w4 = cmul(w2, w2);
    x[1 * S] = cmul(x[1 * S], w1);
    x[2 * S] = cmul(x[2 * S], w2);
    x[3 * S] = cmul(x[3 * S], w3);
    x[4 * S] = cmul(x[4 * S], w4);
    float2 w5 = cmul(w1, w4);
    float2 w6 = cmul(w2, w4);
    float2 w7 = cmul(w3, w4);
    float2 w8 = cmul(w4, w4);
    x[5 * S] = cmul(x[5 * S], w5);
    x[6 * S] = cmul(x[6 * S], w6);
    x[7 * S] = cmul(x[7 * S], w7);
    x[8 * S] = cmul(x[8 * S], w8);
    float2 w9  = cmul(w5, w4);
    float2 w10 = cmul(w6, w4);
    float2 w11 = cmul(w7, w4);
    float2 w12 = cmul(w8, w4);
    x[9 * S]  = cmul(x[9 * S],  w9);
    x[10 * S] = cmul(x[10 * S], w10);
    x[11 * S] = cmul(x[11 * S], w11);
    x[12 * S] = cmul(x[12 * S], w12);
    x[13 * S] = cmul(x[13 * S], cmul(w9, w4));
    x[14 * S] = cmul(x[14 * S], cmul(w10, w4));
    x[15 * S] = cmul(x[15 * S], cmul(w11, w4));
}

// Forward radix-16 stage (NS=16000, m=1000), DIF, paired via float4.
__device__ __forceinline__ void stage16_fwd(float2* sm, int tid) {
    if (tid >= 500) return;
    int n2 = 2 * tid;
    float2 X[32];   // even slots: butterfly A (n2), odd: butterfly B (n2+1)
#pragma unroll
    for (int j = 0; j < 16; j++) {
        float4 t = *(const float4*)&sm[PHI(n2 + j * 1000)];
        X[2 * j]     = make_float2(t.x, t.y);
        X[2 * j + 1] = make_float2(t.z, t.w);
    }
    dft16s<-1, 2>(X);
    dft16s<-1, 2>(X + 1);
    float4 wa = g_twp16[n2];
    float4 wb = g_twp16[n2 + 1];
    apply_tw16_chain<2>(X, make_float2(wa.x, wa.y), make_float2(wa.z, wa.w));
    apply_tw16_chain<2>(X + 1, make_float2(wb.x, wb.y), make_float2(wb.z, wb.w));
#pragma unroll
    for (int j = 0; j < 16; j++) {
        *(float4*)&sm[PHI(n2 + j * 1000)] =
            make_float4(X[2 * j].x, X[2 * j].y, X[2 * j + 1].x, X[2 * j + 1].y);
    }
}

// Forward radix-10 stage, two adjacent butterflies per thread; 800 tasks = BT.
template <int NS>
__device__ __forceinline__ void stage10_paired(float2* sm, int tid, const float4* __restrict__ tab) {
    constexpr int m = NS / 10;
    constexpr int halfm = m / 2;
    int blk = tid / halfm;
    int h = tid - blk * halfm;
    int n2 = 2 * h;
    int base = blk * NS + n2;
    float2 X[20];
#pragma unroll
    for (int j = 0; j < 10; j++) {
        float4 t = *(const float4*)&sm[PHI(base + j * m)];
        X[2 * j]     = make_float2(t.x, t.y);
        X[2 * j + 1] = make_float2(t.z, t.w);
    }
    float4 wa = tab[n2];
    float4 wb = tab[n2 + 1];
    dft10s<-1, 2>(X);
    apply_tw10_pc<2>(X, make_float2(wa.x, wa.y), make_float2(wa.z, wa.w));
    dft10s<-1, 2>(X + 1);
    apply_tw10_pc<2>(X + 1, make_float2(wb.x, wb.y), make_float2(wb.z, wb.w));
#pragma unroll
    for (int j = 0; j < 10; j++) {
        *(float4*)&sm[PHI(base + j * m)] =
            make_float4(X[2 * j].x, X[2 * j].y, X[2 * j + 1].x, X[2 * j + 1].y);
    }
}

// Inverse (DIT) stage on the 8000-point array; (w1,w2) pre-conjugated from table.
template <int R, int NS, bool TO_GMEM>
__device__ __forceinline__ void stage8_inv(float2* s8, int tid, float2* __restrict__ gout2,
                                           const float4* __restrict__ tab) {
    constexpr int m = NS / R;
    constexpr int nb = NH / R;
    for (int u = tid; u < nb; u += BT) {
        int blk = u / m;
        int n2 = u - blk * m;
        int base = blk * NS + n2;
        float2 x[R];
#pragma unroll
        for (int j = 0; j < R; j++) x[j] = s8[PHI8(base + j * m)];
        float4 wv = tab[n2];
        float2 w1 = make_float2(wv.x, wv.y);
        float2 w2 = make_float2(wv.z, wv.w);
        if constexpr (R == 16) {
            apply_tw16_tree<1>(x, w1, w2);
            dft16s<1, 1>(x);
        } else {
            apply_tw10_pc<1>(x, w1, w2);
            dft10s<1, 1>(x);
        }
#pragma unroll
        for (int j = 0; j < R; j++) {
            if constexpr (TO_GMEM) gout2[base + j * m] = x[j];   // c[n] -> (z[2n], z[2n+1])
            else s8[PHI8(base + j * m)] = x[j];
        }
    }
}

__device__ __forceinline__ void pw(float2& A, float2& C, float scale) {
    float2 a = A, c = C;
    float2 Fi = make_float2(a.x + c.x, a.y - c.y);
    float2 Fs = make_float2(a.y + c.y, -(a.x - c.x));
    float2 Z = cmul(Fi, Fs);
    Z.x *= scale; Z.y *= scale;
    A = Z;
    C = make_float2(Z.x, -Z.y);
}

// Pack Z-block (10 values, f = f0+1600t) into 5 C values of the 8000-domain,
// then first inverse stage (radix-5), store at s8[PHI8(5b + j)].
__device__ __forceinline__ void pack_inv5_store(const float2* x, float2 w0,
                                                float2* s8, int b) {
    const float RC[5] = {1.f, 0.80901699437494742f, 0.30901699437494742f,
                         -0.30901699437494742f, -0.80901699437494742f};
    const float RS[5] = {0.f, 0.58778525229247313f, 0.95105651629515357f,
                         0.95105651629515357f, 0.58778525229247313f};
    float2 C[5];
#pragma unroll
    for (int t = 0; t < 5; t++) {
        float2 S = cadd(x[t], x[t + 5]);
        float2 Dd = csub(x[t], x[t + 5]);
        float2 wt = (t == 0) ? w0 : cmul(w0, make_float2(RC[t], RS[t]));
        C[t] = cadd(S, cmuli<1>(cmul(wt, Dd)));
    }
    dft5<1>(C);
    int base = PHI8(5 * b);   // 5b..5b+4 never cross a 50-group
#pragma unroll
    for (int j = 0; j < 5; j++) s8[base + j] = C[j];
}

// Fused middle: forward radix-10 (m=1) + Hermitian pointwise + pack + inverse radix-5.
__device__ __forceinline__ void fused_mid(float2* sm, float2* s8, int tid) {
    const float scale = 0.25f / (float)NFFT;
    int fa, fb;
    if (tid < 799) { fa = tid + 1; fb = 1600 - fa; }
    else           { fa = 0;       fb = 800; }
    int b  = block_of(fa);
    int b2 = block_of(fb);
    int pa = PHI(10 * b);
    int pb = PHI(10 * b2);
    float2 xa[10], xb[10];
#pragma unroll
    for (int k = 0; k < 5; k++) {
        float4 t = *(const float4*)&sm[pa + 2 * k];
        xa[2 * k] = make_float2(t.x, t.y); xa[2 * k + 1] = make_float2(t.z, t.w);
        float4 s = *(const float4*)&sm[pb + 2 * k];
        xb[2 * k] = make_float2(s.x, s.y); xb[2 * k + 1] = make_float2(s.z, s.w);
    }
    dft10s<-1, 1>(xa);
    dft10s<-1, 1>(xb);
    if (tid < 799) {
#pragma unroll
        for (int t = 0; t < 10; t++) pw(xa[t], xb[9 - t], scale);
    } else {
        pw(xa[0], xa[0], scale);
        pw(xa[5], xa[5], scale);
        pw(xa[1], xa[9], scale);
        pw(xa[2], xa[8], scale);
        pw(xa[3], xa[7], scale);
        pw(xa[4], xa[6], scale);
        pw(xb[0], xb[9], scale);
        pw(xb[1], xb[8], scale);
        pw(xb[2], xb[7], scale);
        pw(xb[3], xb[6], scale);
        pw(xb[4], xb[5], scale);
    }
    float2 ta = g_tw[fa]; ta.y = -ta.y;   // e^{+2pi i fa/16000}, coalesced (fa=tid+1)
    float2 tb = g_tw[fb]; tb.y = -tb.y;
    pack_inv5_store(xa, ta, s8, b);
    pack_inv5_store(xb, tb, s8, b2);
}

__global__ void __launch_bounds__(BT) mcb_main_kernel(
    const float* __restrict__ img, const float* __restrict__ seq,
    const int* __restrict__ hv, const float* __restrict__ sv,
    float* __restrict__ out, int d) {
    extern __shared__ float2 sm[];
    float2* s8 = sm + SMPAD;
    const int b = blockIdx.x;
    const int tid = threadIdx.x;

    float4* sm4 = (float4*)sm;
    for (int i = tid; i < SMPAD / 2; i += BT) sm4[i] = make_float4(0.f, 0.f, 0.f, 0.f);
    __syncthreads();

    const float* irow = img + (size_t)b * d;
    const float* qrow = seq + (size_t)b * d;
    for (int i = tid; i < d; i += BT) {
        int h = PHI(hv[i]);
        float s = sv[i];
        atomicAdd(&sm[h].x, irow[i] * s);
        atomicAdd(&sm[h].y, qrow[i] * s);
    }
    __syncthreads();

    float2* orow2 = (float2*)(out + (size_t)b * NFFT);

    // forward 16000: 16 (paired), 10, 10 | fused(10 + pointwise + pack + inv5)
    stage16_fwd(sm, tid);                        __syncthreads();
    stage10_paired<1000>(sm, tid, g_twpf1000);   __syncthreads();
    stage10_paired<100>(sm, tid, g_twpf100);     __syncthreads();
    fused_mid(sm, s8, tid);                      __syncthreads();
    // inverse 8000: 10 (m=5), 10 (m=50), 16 (m=500) -> gmem float2
    stage8_inv<10, 50, false>(s8, tid, orow2, g_twpi50);     __syncthreads();
    stage8_inv<10, 500, false>(s8, tid, orow2, g_twpi500);   __syncthreads();
    stage8_inv<16, 8000, true>(s8, tid, orow2, g_twpi8000);
}

extern "C" void kernel_launch(void* const* d_in, const int* in_sizes, int n_in,
                              void* d_out, int out_size) {
    const float* img = (const float*)d_in[0];
    const float* seq = (const float*)d_in[1];
    const int* hv = (const int*)d_in[2];
    const float* sv = (const float*)d_in[3];
    float* out = (float*)d_out;

    int d = in_sizes[2];
    int B = in_sizes[0] / d;

    static_assert(NFFT == 16000 && NH == 8000, "plan assumes N=16000");

    cudaFuncSetAttribute(mcb_main_kernel, cudaFuncAttributeMaxDynamicSharedMemorySize,
                         SMTOTAL);

    init_tables_kernel<<<(NFFT + 255) / 256, 256>>>();
    mcb_main_kernel<<<B, BT, SMTOTAL>>>(img, seq, hv, sv, out, d);
}

// round 11
// speedup vs baseline: 1.0116x; 1.0116x over previous
#include <cuda_runtime.h>

#define NFFT 16000
#define NH   8000
#define BT   800
// 16000-domain padding (forward stages)
#define PHI(i)  ((i) + 6 * ((i) / 100))
#define SMPAD   (NFFT + 6 * (NFFT / 100))        // 16960 float2
// 8000-domain padding (inverse stages), separate region
#define PHI8(i) ((i) + 3 * ((i) / 50))
#define SMPAD8  (NH + 3 * (NH / 50))             // 8480 float2
#define SMTOTAL ((SMPAD + SMPAD8) * sizeof(float2))  // 203,520 B

// Forward plan (DIF) on 16000: 16,10,10,10 -> strides 1000,100,10,1
// Inverse plan (DIT) on 8000:  [16,10,10,5]; digit maps as in earlier rounds.
// Two rows per block: row B's zero+scatter overlaps row A's inverse stages
// (disjoint SMEM regions sm / s8, same barrier intervals).

__device__ __align__(16) float2 g_tw[NFFT];      // e^{-2*pi*i*t/16000}
__device__ __align__(16) float2 g_twf1000[100];  // g_tw[16*n2]
__device__ __align__(16) float2 g_twf100[16];    // g_tw[160*n2]
__device__ __align__(16) float2 g_twi50[8];      // conj g_tw[320*n2]
__device__ __align__(16) float2 g_twi500[56];    // conj g_tw[32*n2]
__device__ __align__(16) float2 g_twi8000[500];  // conj g_tw[2*n2]

__global__ void init_tables_kernel() {
    int p = blockIdx.x * blockDim.x + threadIdx.x;
    if (p < NFFT) {
        double ang = -6.283185307179586476925286766559 * (double)p / (double)NFFT;
        g_tw[p] = make_float2((float)cos(ang), (float)sin(ang));
    }
    if (p < 100) {
        double a = -6.283185307179586476925286766559 * (double)(16 * p) / (double)NFFT;
        g_twf1000[p] = make_float2((float)cos(a), (float)sin(a));
    }
    if (p < 10) {
        double a = -6.283185307179586476925286766559 * (double)(160 * p) / (double)NFFT;
        g_twf100[p] = make_float2((float)cos(a), (float)sin(a));
    }
    if (p < 5) {
        double a = 6.283185307179586476925286766559 * (double)(320 * p) / (double)NFFT;
        g_twi50[p] = make_float2((float)cos(a), (float)sin(a));
    }
    if (p < 50) {
        double a = 6.283185307179586476925286766559 * (double)(32 * p) / (double)NFFT;
        g_twi500[p] = make_float2((float)cos(a), (float)sin(a));
    }
    if (p < 500) {
        double a = 6.283185307179586476925286766559 * (double)(2 * p) / (double)NFFT;
        g_twi8000[p] = make_float2((float)cos(a), (float)sin(a));
    }
}

__device__ __forceinline__ int block_of(int f0) {
    return 100 * (f0 & 15) + 10 * ((f0 >> 4) % 10) + (f0 / 160);
}

__device__ __forceinline__ float2 cadd(float2 a, float2 b) { return make_float2(a.x + b.x, a.y + b.y); }
__device__ __forceinline__ float2 csub(float2 a, float2 b) { return make_float2(a.x - b.x, a.y - b.y); }
__device__ __forceinline__ float2 cmul(float2 a, float2 b) {
    return make_float2(fmaf(a.x, b.x, -a.y * b.y), fmaf(a.x, b.y, a.y * b.x));
}
__device__ __forceinline__ float2 cmulc(float2 a, float cr, float ci) {
    return make_float2(fmaf(a.x, cr, -a.y * ci), fmaf(a.x, ci, a.y * cr));
}
template <int DIR>
__device__ __forceinline__ float2 cmuli(float2 a) {   // * (DIR*i)
    return (DIR > 0) ? make_float2(-a.y, a.x) : make_float2(a.y, -a.x);
}

template <int DIR>
__device__ __forceinline__ void dft4(float2* x) {
    float2 t0 = cadd(x[0], x[2]);
    float2 t1 = csub(x[0], x[2]);
    float2 t2 = cadd(x[1], x[3]);
    float2 t3 = cmuli<DIR>(csub(x[1], x[3]));
    x[0] = cadd(t0, t2);
    x[2] = csub(t0, t2);
    x[1] = cadd(t1, t3);
    x[3] = csub(t1, t3);
}

template <int DIR>
__device__ __forceinline__ void dft5(float2* x) {
    const float c1 = 0.30901699437494742f;
    const float c2 = -0.80901699437494745f;
    const float s1 = 0.95105651629515357f;
    const float s2 = 0.58778525229247313f;
    float2 t1 = cadd(x[1], x[4]);
    float2 t2 = cadd(x[2], x[3]);
    float2 t3 = csub(x[1], x[4]);
    float2 t4 = csub(x[2], x[3]);
    float2 x0 = x[0];
    float2 a1 = make_float2(x0.x + c1 * t1.x + c2 * t2.x, x0.y + c1 * t1.y + c2 * t2.y);
    float2 a2 = make_float2(x0.x + c2 * t1.x + c1 * t2.x, x0.y + c2 * t1.y + c1 * t2.y);
    float2 b1 = make_float2(s1 * t3.x + s2 * t4.x, s1 * t3.y + s2 * t4.y);
    float2 b2 = make_float2(s2 * t3.x - s1 * t4.x, s2 * t3.y - s1 * t4.y);
    x[0] = make_float2(x0.x + t1.x + t2.x, x0.y + t1.y + t2.y);
    float2 ib1 = cmuli<DIR>(b1);
    float2 ib2 = cmuli<DIR>(b2);
    x[1] = cadd(a1, ib1);
    x[4] = csub(a1, ib1);
    x[2] = cadd(a2, ib2);
    x[3] = csub(a2, ib2);
}

// 10-point DFT = 2x5 CT, stride-S register access.
template <int DIR, int S>
__device__ __forceinline__ void dft10s(float2* x) {
    const float C36 = 0.80901699437494742f;
    const float S36 = 0.58778525229247313f;
    const float C72 = 0.30901699437494742f;
    const float S72 = 0.95105651629515357f;
    const float D = (float)DIR;
    float2 a[5], c[5];
#pragma unroll
    for (int k = 0; k < 5; k++) {
        a[k] = cadd(x[k * S], x[(k + 5) * S]);
        c[k] = csub(x[k * S], x[(k + 5) * S]);
    }
    c[1] = cmulc(c[1], C36, D * S36);
    c[2] = cmulc(c[2], C72, D * S72);
    c[3] = cmulc(c[3], -C72, D * S72);
    c[4] = cmulc(c[4], -C36, D * S36);
    dft5<DIR>(a);
    dft5<DIR>(c);
    x[0 * S] = a[0]; x[2 * S] = a[1]; x[4 * S] = a[2]; x[6 * S] = a[3]; x[8 * S] = a[4];
    x[1 * S] = c[0]; x[3 * S] = c[1]; x[5 * S] = c[2]; x[7 * S] = c[3]; x[9 * S] = c[4];
}

// 16-point DFT = 4x4 CT, stride-S register access.
template <int DIR, int S>
__device__ __forceinline__ void dft16s(float2* x) {
    const float C1 = 0.92387953251128674f;
    const float S1 = 0.38268343236508978f;
    const float C2 = 0.70710678118654752f;
    const float D = (float)DIR;
    float2 y[16];
#pragma unroll
    for (int n2 = 0; n2 < 4; n2++) {
        float2 t[4] = {x[n2 * S], x[(n2 + 4) * S], x[(n2 + 8) * S], x[(n2 + 12) * S]};
        dft4<DIR>(t);
        if (n2 == 1) {
            t[1] = cmulc(t[1], C1, D * S1);
            t[2] = cmulc(t[2], C2, D * C2);
            t[3] = cmulc(t[3], S1, D * C1);
        } else if (n2 == 2) {
            t[1] = cmulc(t[1], C2, D * C2);
            t[2] = cmuli<DIR>(t[2]);
            t[3] = cmulc(t[3], -C2, D * C2);
        } else if (n2 == 3) {
            t[1] = cmulc(t[1], S1, D * C1);
            t[2] = cmulc(t[2], -C2, D * C2);
            t[3] = cmulc(t[3], -C1, -D * S1);
        }
        y[0 + n2] = t[0]; y[4 + n2] = t[1]; y[8 + n2] = t[2]; y[12 + n2] = t[3];
    }
#pragma unroll
    for (int k1 = 0; k1 < 4; k1++) {
        float2 t[4] = {y[k1 * 4 + 0], y[k1 * 4 + 1], y[k1 * 4 + 2], y[k1 * 4 + 3]};
        dft4<DIR>(t);
        x[(k1 + 0) * S] = t[0]; x[(k1 + 4) * S] = t[1];
        x[(k1 + 8) * S] = t[2]; x[(k1 + 12) * S] = t[3];
    }
}

// Twiddle application: odd/even accumulator chains stepping by w^2.
template <int S>
__device__ __forceinline__ void apply_tw10_chain(float2* x, float2 w1) {
    float2 w2 = cmul(w1, w1);
    float2 wo = w1, we = w2;
    x[1 * S] = cmul(x[1 * S], wo);
    x[2 * S] = cmul(x[2 * S], we);
#pragma unroll
    for (int j = 3; j < 10; j += 2) {
        wo = cmul(wo, w2); x[j * S] = cmul(x[j * S], wo);
        if (j + 1 < 10) { we = cmul(we, w2); x[(j + 1) * S] = cmul(x[(j + 1) * S], we); }
    }
}

template <int S>
__device__ __forceinline__ void apply_tw16_chain(float2* x, float2 w1) {
    float2 w2 = cmul(w1, w1);
    float2 wo = w1, we = w2;
    x[1 * S] = cmul(x[1 * S], wo);
    x[2 * S] = cmul(x[2 * S], we);
#pragma unroll
    for (int j = 3; j < 16; j += 2) {
        wo = cmul(wo, w2); x[j * S] = cmul(x[j * S], wo);
        if (j + 1 < 16) { we = cmul(we, w2); x[(j + 1) * S] = cmul(x[(j + 1) * S], we); }
    }
}

// Forward radix-16 stage (NS=16000, m=1000), DIF, paired via float4.
__device__ __forceinline__ void stage16_fwd(float2* sm, int tid) {
    if (tid >= 500) return;
    int n2 = 2 * tid;
    float2 X[32];   // even slots: butterfly A (n2), odd: butterfly B (n2+1)
#pragma unroll
    for (int j = 0; j < 16; j++) {
        float4 t = *(const float4*)&sm[PHI(n2 + j * 1000)];
        X[2 * j]     = make_float2(t.x, t.y);
        X[2 * j + 1] = make_float2(t.z, t.w);
    }
    dft16s<-1, 2>(X);
    dft16s<-1, 2>(X + 1);
    float4 wv = *(const float4*)&g_tw[n2];
    apply_tw16_chain<2>(X, make_float2(wv.x, wv.y));
    apply_tw16_chain<2>(X + 1, make_float2(wv.z, wv.w));
#pragma unroll
    for (int j = 0; j < 16; j++) {
        *(float4*)&sm[PHI(n2 + j * 1000)] =
            make_float4(X[2 * j].x, X[2 * j].y, X[2 * j + 1].x, X[2 * j + 1].y);
    }
}

// Forward radix-10 stage, two adjacent butterflies per thread; 800 tasks = BT.
template <int NS>
__device__ __forceinline__ void stage10_paired(float2* sm, int tid, const float2* __restrict__ tab) {
    constexpr int m = NS / 10;
    constexpr int halfm = m / 2;
    int blk = tid / halfm;
    int h = tid - blk * halfm;
    int n2 = 2 * h;
    int base = blk * NS + n2;
    float2 X[20];
#pragma unroll
    for (int j = 0; j < 10; j++) {
        float4 t = *(const float4*)&sm[PHI(base + j * m)];
        X[2 * j]     = make_float2(t.x, t.y);
        X[2 * j + 1] = make_float2(t.z, t.w);
    }
    float4 wv = *(const float4*)&tab[n2];
    dft10s<-1, 2>(X);
    apply_tw10_chain<2>(X, make_float2(wv.x, wv.y));
    dft10s<-1, 2>(X + 1);
    apply_tw10_chain<2>(X + 1, make_float2(wv.z, wv.w));
#pragma unroll
    for (int j = 0; j < 10; j++) {
        *(float4*)&sm[PHI(base + j * m)] =
            make_float4(X[2 * j].x, X[2 * j].y, X[2 * j + 1].x, X[2 * j + 1].y);
    }
}

// Inverse (DIT) stage on the 8000-point array; w1 from pre-conjugated coalesced table.
template <int R, int NS, bool TO_GMEM>
__device__ __forceinline__ void stage8_inv(float2* s8, int tid, float2* __restrict__ gout2,
                                           const float2* __restrict__ tab) {
    constexpr int m = NS / R;
    constexpr int nb = NH / R;
    for (int u = tid; u < nb; u += BT) {
        int blk = u / m;
        int n2 = u - blk * m;
        int base = blk * NS + n2;
        float2 x[R];
#pragma unroll
        for (int j = 0; j < R; j++) x[j] = s8[PHI8(base + j * m)];
        float2 w1 = tab[n2];
        if constexpr (R == 16) {
            apply_tw16_chain<1>(x, w1);
            dft16s<1, 1>(x);
        } else {
            apply_tw10_chain<1>(x, w1);
            dft10s<1, 1>(x);
        }
#pragma unroll
        for (int j = 0; j < R; j++) {
            if constexpr (TO_GMEM) gout2[base + j * m] = x[j];   // c[n] -> (z[2n], z[2n+1])
            else s8[PHI8(base + j * m)] = x[j];
        }
    }
}

__device__ __forceinline__ void pw(float2& A, float2& C, float scale) {
    float2 a = A, c = C;
    float2 Fi = make_float2(a.x + c.x, a.y - c.y);
    float2 Fs = make_float2(a.y + c.y, -(a.x - c.x));
    float2 Z = cmul(Fi, Fs);
    Z.x *= scale; Z.y *= scale;
    A = Z;
    C = make_float2(Z.x, -Z.y);
}

// Pack Z-block (10 values, f = f0+1600t) into 5 C values of the 8000-domain,
// then first inverse stage (radix-5), store at s8[PHI8(5b + j)].
__device__ __forceinline__ void pack_inv5_store(const float2* x, float2 w0,
                                                float2* s8, int b) {
    const float RC[5] = {1.f, 0.80901699437494742f, 0.30901699437494742f,
                         -0.30901699437494742f, -0.80901699437494742f};
    const float RS[5] = {0.f, 0.58778525229247313f, 0.95105651629515357f,
                         0.95105651629515357f, 0.58778525229247313f};
    float2 C[5];
#pragma unroll
    for (int t = 0; t < 5; t++) {
        float2 S = cadd(x[t], x[t + 5]);
        float2 Dd = csub(x[t], x[t + 5]);
        float2 wt = (t == 0) ? w0 : cmul(w0, make_float2(RC[t], RS[t]));
        C[t] = cadd(S, cmuli<1>(cmul(wt, Dd)));
    }
    dft5<1>(C);
    int base = PHI8(5 * b);   // 5b..5b+4 never cross a 50-group
#pragma unroll
    for (int j = 0; j < 5; j++) s8[base + j] = C[j];
}

// Fused middle: forward radix-10 (m=1) + Hermitian pointwise + pack + inverse radix-5.
__device__ __forceinline__ void fused_mid(float2* sm, float2* s8, int tid) {
    const float scale = 0.25f / (float)NFFT;
    int fa, fb;
    if (tid < 799) { fa = tid + 1; fb = 1600 - fa; }
    else           { fa = 0;       fb = 800; }
    int b  = block_of(fa);
    int b2 = block_of(fb);
    int pa = PHI(10 * b);
    int pb = PHI(10 * b2);
    float2 xa[10], xb[10];
#pragma unroll
    for (int k = 0; k < 5; k++) {
        float4 t = *(const float4*)&sm[pa + 2 * k];
        xa[2 * k] = make_float2(t.x, t.y); xa[2 * k + 1] = make_float2(t.z, t.w);
        float4 s = *(const float4*)&sm[pb + 2 * k];
        xb[2 * k] = make_float2(s.x, s.y); xb[2 * k + 1] = make_float2(s.z, s.w);
    }
    dft10s<-1, 1>(xa);
    dft10s<-1, 1>(xb);
    if (tid < 799) {
#pragma unroll
        for (int t = 0; t < 10; t++) pw(xa[t], xb[9 - t], scale);
    } else {
        pw(xa[0], xa[0], scale);
        pw(xa[5], xa[5], scale);
        pw(xa[1], xa[9], scale);
        pw(xa[2], xa[8], scale);
        pw(xa[3], xa[7], scale);
        pw(xa[4], xa[6], scale);
        pw(xb[0], xb[9], scale);
        pw(xb[1], xb[8], scale);
        pw(xb[2], xb[7], scale);
        pw(xb[3], xb[6], scale);
        pw(xb[4], xb[5], scale);
    }
    float2 ta = g_tw[fa]; ta.y = -ta.y;   // e^{+2pi i fa/16000}, coalesced (fa=tid+1)
    float2 tb = g_tw[fb]; tb.y = -tb.y;
    pack_inv5_store(xa, ta, s8, b);
    pack_inv5_store(xb, tb, s8, b2);
}

// ---- prologue helpers (row-local) ----
__device__ __forceinline__ void zero_sm(float2* sm, int tid) {
    float4* sm4 = (float4*)sm;
    for (int i = tid; i < SMPAD / 2; i += BT) sm4[i] = make_float4(0.f, 0.f, 0.f, 0.f);
}
__device__ __forceinline__ void scatter_row(float2* sm, const float* __restrict__ img,
                                            const float* __restrict__ seq,
                                            const int* __restrict__ hv,
                                            const float* __restrict__ sv,
                                            int d, int row, int tid) {
    const float* irow = img + (size_t)row * d;
    const float* qrow = seq + (size_t)row * d;
    for (int i = tid; i < d; i += BT) {
        int h = PHI(hv[i]);
        float s = sv[i];
        atomicAdd(&sm[h].x, irow[i] * s);
        atomicAdd(&sm[h].y, qrow[i] * s);
    }
}

// Forward + fused middle for one row already scattered into sm.
__device__ __forceinline__ void forward_and_mid(float2* sm, float2* s8, int tid) {
    stage16_fwd(sm, tid);                       __syncthreads();
    stage10_paired<1000>(sm, tid, g_twf1000);   __syncthreads();
    stage10_paired<100>(sm, tid, g_twf100);     __syncthreads();
    fused_mid(sm, s8, tid);                     __syncthreads();
}

__global__ void __launch_bounds__(BT) mcb_main_kernel(
    const float* __restrict__ img, const float* __restrict__ seq,
    const int* __restrict__ hv, const float* __restrict__ sv,
    float* __restrict__ out, int d, int B) {
    extern __shared__ float2 sm[];
    float2* s8 = sm + SMPAD;
    const int tid = threadIdx.x;
    const int rowA = 2 * blockIdx.x;
    const int rowB = rowA + 1;
    const bool hasB = (rowB < B);

    float2* orowA = (float2*)(out + (size_t)rowA * NFFT);

    // --- row A prologue ---
    zero_sm(sm, tid);
    __syncthreads();
    scatter_row(sm, img, seq, hv, sv, d, rowA, tid);
    __syncthreads();

    // --- row A forward + fused middle (sm -> s8); sm dead afterwards ---
    forward_and_mid(sm, s8, tid);

    // --- row A inverse, overlapped with row B prologue (disjoint regions) ---
    stage8_inv<10, 50, false>(s8, tid, orowA, g_twi50);
    zero_sm(sm, tid);                 // row B zero-init hides under inv50 latency
    __syncthreads();
    stage8_inv<10, 500, false>(s8, tid, orowA, g_twi500);
    if (hasB) scatter_row(sm, img, seq, hv, sv, d, rowB, tid);  // hides under inv500
    __syncthreads();
    stage8_inv<16, 8000, true>(s8, tid, orowA, g_twi8000);

    if (!hasB) return;
    __syncthreads();

    // --- row B full pipeline (prologue already done) ---
    float2* orowB = (float2*)(out + (size_t)rowB * NFFT);
    forward_and_mid(sm, s8, tid);
    stage8_inv<10, 50, false>(s8, tid, orowB, g_twi50);     __syncthreads();
    stage8_inv<10, 500, false>(s8, tid, orowB, g_twi500);   __syncthreads();
    stage8_inv<16, 8000, true>(s8, tid, orowB, g_twi8000);
}

extern "C" void kernel_launch(void* const* d_in, const int* in_sizes, int n_in,
                              void* d_out, int out_size) {
    const float* img = (const float*)d_in[0];
    const float* seq = (const float*)d_in[1];
    const int* hv = (const int*)d_in[2];
    const float* sv = (const float*)d_in[3];
    float* out = (float*)d_out;

    int d = in_sizes[2];
    int B = in_sizes[0] / d;
    int nblk = (B + 1) / 2;

    static_assert(NFFT == 16000 && NH == 8000, "plan assumes N=16000");

    cudaFuncSetAttribute(mcb_main_kernel, cudaFuncAttributeMaxDynamicSharedMemorySize,
                         SMTOTAL);

    init_tables_kernel<<<(NFFT + 255) / 256, 256>>>();
    mcb_main_kernel<<<nblk, BT, SMTOTAL>>>(img, seq, hv, sv, out, d, B);
}

// round 12
// speedup vs baseline: 1.0670x; 1.0548x over previous
#include <cuda_runtime.h>

#define NFFT 16000
#define NH   8000
#define BT   800
#define DMAX 4096
// 16000-domain padding (forward stages)
#define PHI(i)  ((i) + 6 * ((i) / 100))
#define SMPAD   (NFFT + 6 * (NFFT / 100))        // 16960 float2
// 8000-domain padding (inverse stages), separate region
#define PHI8(i) ((i) + 3 * ((i) / 50))
#define SMPAD8  (NH + 3 * (NH / 50))             // 8480 float2
#define SMTOTAL ((SMPAD + SMPAD8) * sizeof(float2))  // 203,520 B

// Forward plan (DIF) on 16000: 16,10,10,10 -> strides 1000,100,10,1
// Inverse plan (DIT) on 8000:  [16,10,10,5]; digit maps as in earlier rounds.

__device__ __align__(16) float2 g_tw[NFFT];      // e^{-2*pi*i*t/16000}
__device__ __align__(16) float2 g_twf1000[100];  // g_tw[16*n2]
__device__ __align__(16) float2 g_twf100[16];    // g_tw[160*n2]
__device__ __align__(16) float2 g_twi50[8];      // conj g_tw[320*n2]
__device__ __align__(16) float2 g_twi500[56];    // conj g_tw[32*n2]
__device__ __align__(16) float2 g_twi8000[500];  // conj g_tw[2*n2]
__device__ int g_hphi[DMAX];                     // PHI(h_vec[i])
// per-thread fused_mid addresses: low16 = PHI(10*b) (fwd smem), high16 = PHI8(5*b) (inv smem)
__device__ int g_pairsA[BT];
__device__ int g_pairsB[BT];

__device__ __forceinline__ int block_of_host(int f0) {
    return 100 * (f0 & 15) + 10 * ((f0 >> 4) % 10) + (f0 / 160);
}

__global__ void init_tables_kernel(const int* __restrict__ hv, int d) {
    int p = blockIdx.x * blockDim.x + threadIdx.x;
    if (p < NFFT) {
        double ang = -6.283185307179586476925286766559 * (double)p / (double)NFFT;
        g_tw[p] = make_float2((float)cos(ang), (float)sin(ang));
    }
    if (p < 100) {
        double a = -6.283185307179586476925286766559 * (double)(16 * p) / (double)NFFT;
        g_twf1000[p] = make_float2((float)cos(a), (float)sin(a));
    }
    if (p < 10) {
        double a = -6.283185307179586476925286766559 * (double)(160 * p) / (double)NFFT;
        g_twf100[p] = make_float2((float)cos(a), (float)sin(a));
    }
    if (p < 5) {
        double a = 6.283185307179586476925286766559 * (double)(320 * p) / (double)NFFT;
        g_twi50[p] = make_float2((float)cos(a), (float)sin(a));
    }
    if (p < 50) {
        double a = 6.283185307179586476925286766559 * (double)(32 * p) / (double)NFFT;
        g_twi500[p] = make_float2((float)cos(a), (float)sin(a));
    }
    if (p < 500) {
        double a = 6.283185307179586476925286766559 * (double)(2 * p) / (double)NFFT;
        g_twi8000[p] = make_float2((float)cos(a), (float)sin(a));
    }
    if (p < d && p < DMAX) {
        int h = hv[p];
        g_hphi[p] = PHI(h);
    }
    if (p < BT) {
        int fa, fb;
        if (p < 799) { fa = p + 1; fb = 1600 - fa; }
        else         { fa = 0;     fb = 800; }
        int ba = block_of_host(fa);
        int bb = block_of_host(fb);
        int paf = PHI(10 * ba);
        int pbf = PHI(10 * bb);
        int pai = PHI8(5 * ba);
        int pbi = PHI8(5 * bb);
        g_pairsA[p] = paf | (pai << 16);
        g_pairsB[p] = pbf | (pbi << 16);
    }
}

__device__ __forceinline__ float2 cadd(float2 a, float2 b) { return make_float2(a.x + b.x, a.y + b.y); }
__device__ __forceinline__ float2 csub(float2 a, float2 b) { return make_float2(a.x - b.x, a.y - b.y); }
__device__ __forceinline__ float2 cmul(float2 a, float2 b) {
    return make_float2(fmaf(a.x, b.x, -a.y * b.y), fmaf(a.x, b.y, a.y * b.x));
}
__device__ __forceinline__ float2 cmulc(float2 a, float cr, float ci) {
    return make_float2(fmaf(a.x, cr, -a.y * ci), fmaf(a.x, ci, a.y * cr));
}
template <int DIR>
__device__ __forceinline__ float2 cmuli(float2 a) {   // * (DIR*i)
    return (DIR > 0) ? make_float2(-a.y, a.x) : make_float2(a.y, -a.x);
}

template <int DIR>
__device__ __forceinline__ void dft4(float2* x) {
    float2 t0 = cadd(x[0], x[2]);
    float2 t1 = csub(x[0], x[2]);
    float2 t2 = cadd(x[1], x[3]);
    float2 t3 = cmuli<DIR>(csub(x[1], x[3]));
    x[0] = cadd(t0, t2);
    x[2] = csub(t0, t2);
    x[1] = cadd(t1, t3);
    x[3] = csub(t1, t3);
}

template <int DIR>
__device__ __forceinline__ void dft5(float2* x) {
    const float c1 = 0.30901699437494742f;
    const float c2 = -0.80901699437494745f;
    const float s1 = 0.95105651629515357f;
    const float s2 = 0.58778525229247313f;
    float2 t1 = cadd(x[1], x[4]);
    float2 t2 = cadd(x[2], x[3]);
    float2 t3 = csub(x[1], x[4]);
    float2 t4 = csub(x[2], x[3]);
    float2 x0 = x[0];
    float2 a1 = make_float2(x0.x + c1 * t1.x + c2 * t2.x, x0.y + c1 * t1.y + c2 * t2.y);
    float2 a2 = make_float2(x0.x + c2 * t1.x + c1 * t2.x, x0.y + c2 * t1.y + c1 * t2.y);
    float2 b1 = make_float2(s1 * t3.x + s2 * t4.x, s1 * t3.y + s2 * t4.y);
    float2 b2 = make_float2(s2 * t3.x - s1 * t4.x, s2 * t3.y - s1 * t4.y);
    x[0] = make_float2(x0.x + t1.x + t2.x, x0.y + t1.y + t2.y);
    float2 ib1 = cmuli<DIR>(b1);
    float2 ib2 = cmuli<DIR>(b2);
    x[1] = cadd(a1, ib1);
    x[4] = csub(a1, ib1);
    x[2] = cadd(a2, ib2);
    x[3] = csub(a2, ib2);
}

// 10-point DFT = 2x5 CT, stride-S register access.
template <int DIR, int S>
__device__ __forceinline__ void dft10s(float2* x) {
    const float C36 = 0.80901699437494742f;
    const float S36 = 0.58778525229247313f;
    const float C72 = 0.30901699437494742f;
    const float S72 = 0.95105651629515357f;
    const float D = (float)DIR;
    float2 a[5], c[5];
#pragma unroll
    for (int k = 0; k < 5; k++) {
        a[k] = cadd(x[k * S], x[(k + 5) * S]);
        c[k] = csub(x[k * S], x[(k + 5) * S]);
    }
    c[1] = cmulc(c[1], C36, D * S36);
    c[2] = cmulc(c[2], C72, D * S72);
    c[3] = cmulc(c[3], -C72, D * S72);
    c[4] = cmulc(c[4], -C36, D * S36);
    dft5<DIR>(a);
    dft5<DIR>(c);
    x[0 * S] = a[0]; x[2 * S] = a[1]; x[4 * S] = a[2]; x[6 * S] = a[3]; x[8 * S] = a[4];
    x[1 * S] = c[0]; x[3 * S] = c[1]; x[5 * S] = c[2]; x[7 * S] = c[3]; x[9 * S] = c[4];
}

// 16-point DFT = 4x4 CT, stride-S register access.
template <int DIR, int S>
__device__ __forceinline__ void dft16s(float2* x) {
    const float C1 = 0.92387953251128674f;
    const float S1 = 0.38268343236508978f;
    const float C2 = 0.70710678118654752f;
    const float D = (float)DIR;
    float2 y[16];
#pragma unroll
    for (int n2 = 0; n2 < 4; n2++) {
        float2 t[4] = {x[n2 * S], x[(n2 + 4) * S], x[(n2 + 8) * S], x[(n2 + 12) * S]};
        dft4<DIR>(t);
        if (n2 == 1) {
            t[1] = cmulc(t[1], C1, D * S1);
            t[2] = cmulc(t[2], C2, D * C2);
            t[3] = cmulc(t[3], S1, D * C1);
        } else if (n2 == 2) {
            t[1] = cmulc(t[1], C2, D * C2);
            t[2] = cmuli<DIR>(t[2]);
            t[3] = cmulc(t[3], -C2, D * C2);
        } else if (n2 == 3) {
            t[1] = cmulc(t[1], S1, D * C1);
            t[2] = cmulc(t[2], -C2, D * C2);
            t[3] = cmulc(t[3], -C1, -D * S1);
        }
        y[0 + n2] = t[0]; y[4 + n2] = t[1]; y[8 + n2] = t[2]; y[12 + n2] = t[3];
    }
#pragma unroll
    for (int k1 = 0; k1 < 4; k1++) {
        float2 t[4] = {y[k1 * 4 + 0], y[k1 * 4 + 1], y[k1 * 4 + 2], y[k1 * 4 + 3]};
        dft4<DIR>(t);
        x[(k1 + 0) * S] = t[0]; x[(k1 + 4) * S] = t[1];
        x[(k1 + 8) * S] = t[2]; x[(k1 + 12) * S] = t[3];
    }
}

// Twiddle application: odd/even accumulator chains stepping by w^2.
template <int S>
__device__ __forceinline__ void apply_tw10_chain(float2* x, float2 w1) {
    float2 w2 = cmul(w1, w1);
    float2 wo = w1, we = w2;
    x[1 * S] = cmul(x[1 * S], wo);
    x[2 * S] = cmul(x[2 * S], we);
#pragma unroll
    for (int j = 3; j < 10; j += 2) {
        wo = cmul(wo, w2); x[j * S] = cmul(x[j * S], wo);
        if (j + 1 < 10) { we = cmul(we, w2); x[(j + 1) * S] = cmul(x[(j + 1) * S], we); }
    }
}

template <int S>
__device__ __forceinline__ void apply_tw16_chain(float2* x, float2 w1) {
    float2 w2 = cmul(w1, w1);
    float2 wo = w1, we = w2;
    x[1 * S] = cmul(x[1 * S], wo);
    x[2 * S] = cmul(x[2 * S], we);
#pragma unroll
    for (int j = 3; j < 16; j += 2) {
        wo = cmul(wo, w2); x[j * S] = cmul(x[j * S], wo);
        if (j + 1 < 16) { we = cmul(we, w2); x[(j + 1) * S] = cmul(x[(j + 1) * S], we); }
    }
}

// Forward radix-16 stage (NS=16000, m=1000), DIF, paired via float4.
__device__ __forceinline__ void stage16_fwd(float2* sm, int tid) {
    if (tid >= 500) return;
    int n2 = 2 * tid;
    float2 X[32];   // even slots: butterfly A (n2), odd: butterfly B (n2+1)
#pragma unroll
    for (int j = 0; j < 16; j++) {
        float4 t = *(const float4*)&sm[PHI(n2 + j * 1000)];
        X[2 * j]     = make_float2(t.x, t.y);
        X[2 * j + 1] = make_float2(t.z, t.w);
    }
    dft16s<-1, 2>(X);
    dft16s<-1, 2>(X + 1);
    float4 wv = *(const float4*)&g_tw[n2];
    apply_tw16_chain<2>(X, make_float2(wv.x, wv.y));
    apply_tw16_chain<2>(X + 1, make_float2(wv.z, wv.w));
#pragma unroll
    for (int j = 0; j < 16; j++) {
        *(float4*)&sm[PHI(n2 + j * 1000)] =
            make_float4(X[2 * j].x, X[2 * j].y, X[2 * j + 1].x, X[2 * j + 1].y);
    }
}

// Forward radix-10 stage, two adjacent butterflies per thread; 800 tasks = BT.
template <int NS>
__device__ __forceinline__ void stage10_paired(float2* sm, int tid, const float2* __restrict__ tab) {
    constexpr int m = NS / 10;
    constexpr int halfm = m / 2;
    int blk = tid / halfm;
    int h = tid - blk * halfm;
    int n2 = 2 * h;
    int base = blk * NS + n2;
    float2 X[20];
#pragma unroll
    for (int j = 0; j < 10; j++) {
        float4 t = *(const float4*)&sm[PHI(base + j * m)];
        X[2 * j]     = make_float2(t.x, t.y);
        X[2 * j + 1] = make_float2(t.z, t.w);
    }
    float4 wv = *(const float4*)&tab[n2];
    dft10s<-1, 2>(X);
    apply_tw10_chain<2>(X, make_float2(wv.x, wv.y));
    dft10s<-1, 2>(X + 1);
    apply_tw10_chain<2>(X + 1, make_float2(wv.z, wv.w));
#pragma unroll
    for (int j = 0; j < 10; j++) {
        *(float4*)&sm[PHI(base + j * m)] =
            make_float4(X[2 * j].x, X[2 * j].y, X[2 * j + 1].x, X[2 * j + 1].y);
    }
}

// Inverse (DIT) stage on the 8000-point array; w1 from pre-conjugated coalesced table.
template <int R, int NS, bool TO_GMEM>
__device__ __forceinline__ void stage8_inv(float2* s8, int tid, float2* __restrict__ gout2,
                                           const float2* __restrict__ tab) {
    constexpr int m = NS / R;
    constexpr int nb = NH / R;
    for (int u = tid; u < nb; u += BT) {
        int blk = u / m;
        int n2 = u - blk * m;
        int base = blk * NS + n2;
        float2 x[R];
#pragma unroll
        for (int j = 0; j < R; j++) x[j] = s8[PHI8(base + j * m)];
        float2 w1 = tab[n2];
        if constexpr (R == 16) {
            apply_tw16_chain<1>(x, w1);
            dft16s<1, 1>(x);
        } else {
            apply_tw10_chain<1>(x, w1);
            dft10s<1, 1>(x);
        }
#pragma unroll
        for (int j = 0; j < R; j++) {
            if constexpr (TO_GMEM) gout2[base + j * m] = x[j];   // c[n] -> (z[2n], z[2n+1])
            else s8[PHI8(base + j * m)] = x[j];
        }
    }
}

__device__ __forceinline__ void pw(float2& A, float2& C, float scale) {
    float2 a = A, c = C;
    float2 Fi = make_float2(a.x + c.x, a.y - c.y);
    float2 Fs = make_float2(a.y + c.y, -(a.x - c.x));
    float2 Z = cmul(Fi, Fs);
    Z.x *= scale; Z.y *= scale;
    A = Z;
    C = make_float2(Z.x, -Z.y);
}

// Pack Z-block (10 values, f = f0+1600t) into 5 C values of the 8000-domain,
// then first inverse stage (radix-5); store at s8[base8 + j] (precomputed PHI8(5b)).
__device__ __forceinline__ void pack_inv5_store(const float2* x, float2 w0,
                                                float2* s8, int base8) {
    const float RC[5] = {1.f, 0.80901699437494742f, 0.30901699437494742f,
                         -0.30901699437494742f, -0.80901699437494742f};
    const float RS[5] = {0.f, 0.58778525229247313f, 0.95105651629515357f,
                         0.95105651629515357f, 0.58778525229247313f};
    float2 C[5];
#pragma unroll
    for (int t = 0; t < 5; t++) {
        float2 S = cadd(x[t], x[t + 5]);
        float2 Dd = csub(x[t], x[t + 5]);
        float2 wt = (t == 0) ? w0 : cmul(w0, make_float2(RC[t], RS[t]));
        C[t] = cadd(S, cmuli<1>(cmul(wt, Dd)));
    }
    dft5<1>(C);
#pragma unroll
    for (int j = 0; j < 5; j++) s8[base8 + j] = C[j];
}

// Fused middle: forward radix-10 (m=1) + Hermitian pointwise + pack + inverse radix-5.
// All addresses precomputed in g_pairsA/B (coalesced LDG.32 per thread).
__device__ __forceinline__ void fused_mid(float2* sm, float2* s8, int tid) {
    const float scale = 0.25f / (float)NFFT;
    int pkA = g_pairsA[tid];
    int pkB = g_pairsB[tid];
    int pa = pkA & 0xFFFF, qa = pkA >> 16;   // fwd smem base, inv smem base (row A block)
    int pb = pkB & 0xFFFF, qb = pkB >> 16;
    int fa, fb;
    if (tid < 799) { fa = tid + 1; fb = 1600 - fa; }
    else           { fa = 0;       fb = 800; }
    float2 xa[10], xb[10];
#pragma unroll
    for (int k = 0; k < 5; k++) {
        float4 t = *(const float4*)&sm[pa + 2 * k];
        xa[2 * k] = make_float2(t.x, t.y); xa[2 * k + 1] = make_float2(t.z, t.w);
        float4 s = *(const float4*)&sm[pb + 2 * k];
        xb[2 * k] = make_float2(s.x, s.y); xb[2 * k + 1] = make_float2(s.z, s.w);
    }
    dft10s<-1, 1>(xa);
    dft10s<-1, 1>(xb);
    if (tid < 799) {
#pragma unroll
        for (int t = 0; t < 10; t++) pw(xa[t], xb[9 - t], scale);
    } else {
        pw(xa[0], xa[0], scale);
        pw(xa[5], xa[5], scale);
        pw(xa[1], xa[9], scale);
        pw(xa[2], xa[8], scale);
        pw(xa[3], xa[7], scale);
        pw(xa[4], xa[6], scale);
        pw(xb[0], xb[9], scale);
        pw(xb[1], xb[8], scale);
        pw(xb[2], xb[7], scale);
        pw(xb[3], xb[6], scale);
        pw(xb[4], xb[5], scale);
    }
    float2 ta = g_tw[fa]; ta.y = -ta.y;   // e^{+2pi i fa/16000}, coalesced (fa=tid+1)
    float2 tb = g_tw[fb]; tb.y = -tb.y;
    pack_inv5_store(xa, ta, s8, qa);
    pack_inv5_store(xb, tb, s8, qb);
}

__global__ void __launch_bounds__(BT) mcb_main_kernel(
    const float* __restrict__ img, const float* __restrict__ seq,
    const float* __restrict__ sv,
    float* __restrict__ out, int d) {
    extern __shared__ float2 sm[];
    float2* s8 = sm + SMPAD;
    const int b = blockIdx.x;
    const int tid = threadIdx.x;

    float4* sm4 = (float4*)sm;
    for (int i = tid; i < SMPAD / 2; i += BT) sm4[i] = make_float4(0.f, 0.f, 0.f, 0.f);
    __syncthreads();

    const float* irow = img + (size_t)b * d;
    const float* qrow = seq + (size_t)b * d;
    for (int i = tid; i < d; i += BT) {
        int h = g_hphi[i];          // PHI(h_vec[i]) precomputed
        float s = sv[i];
        atomicAdd(&sm[h].x, irow[i] * s);
        atomicAdd(&sm[h].y, qrow[i] * s);
    }
    __syncthreads();

    float2* orow2 = (float2*)(out + (size_t)b * NFFT);

    // forward 16000: 16 (paired), 10, 10 | fused(10 + pointwise + pack + inv5)
    stage16_fwd(sm, tid);                        __syncthreads();
    stage10_paired<1000>(sm, tid, g_twf1000);    __syncthreads();
    stage10_paired<100>(sm, tid, g_twf100);      __syncthreads();
    fused_mid(sm, s8, tid);                      __syncthreads();
    // inverse 8000: 10 (m=5), 10 (m=50), 16 (m=500) -> gmem float2
    stage8_inv<10, 50, false>(s8, tid, orow2, g_twi50);     __syncthreads();
    stage8_inv<10, 500, false>(s8, tid, orow2, g_twi500);   __syncthreads();
    stage8_inv<16, 8000, true>(s8, tid, orow2, g_twi8000);
}

extern "C" void kernel_launch(void* const* d_in, const int* in_sizes, int n_in,
                              void* d_out, int out_size) {
    const float* img = (const float*)d_in[0];
    const float* seq = (const float*)d_in[1];
    const int* hv = (const int*)d_in[2];
    const float* sv = (const float*)d_in[3];
    float* out = (float*)d_out;

    int d = in_sizes[2];
    int B = in_sizes[0] / d;

    static_assert(NFFT == 16000 && NH == 8000, "plan assumes N=16000");

    cudaFuncSetAttribute(mcb_main_kernel, cudaFuncAttributeMaxDynamicSharedMemorySize,
                         SMTOTAL);

    init_tables_kernel<<<(NFFT + 255) / 256, 256>>>(hv, d);
    mcb_main_kernel<<<B, BT, SMTOTAL>>>(img, seq, sv, out, d);
}

// round 13
// speedup vs baseline: 1.1661x; 1.0929x over previous
#include <cuda_runtime.h>

#define NFFT 16000
#define NH   8000
#define BT   800
// 16000-domain padding (forward stages)
#define PHI(i)  ((i) + 6 * ((i) / 100))
#define SMPAD   (NFFT + 6 * (NFFT / 100))        // 16960 float2
// 8000-domain padding (inverse stages), separate region
#define PHI8(i) ((i) + 3 * ((i) / 50))
#define SMPAD8  (NH + 3 * (NH / 50))             // 8480 float2
#define SMTOTAL ((SMPAD + SMPAD8) * sizeof(float2))  // 203,520 B

// Forward plan (DIF) on 16000: 16,10,10,10 -> strides 1000,100,10,1
// Inverse plan (DIT) on 8000:  [16,10,10,5]; digit maps as in earlier rounds.

__device__ __align__(16) float2 g_tw[NFFT];      // e^{-2*pi*i*t/16000}
__device__ __align__(16) float2 g_twf1000[100];  // g_tw[16*n2]
__device__ __align__(16) float2 g_twf100[16];    // g_tw[160*n2]
__device__ __align__(16) float2 g_twi50[8];      // conj g_tw[320*n2]
__device__ __align__(16) float2 g_twi500[56];    // conj g_tw[32*n2]
__device__ __align__(16) float2 g_twi8000[500];  // conj g_tw[2*n2]

// Flat init: ONE sincospif per thread (no serial double-precision trig chains —
// the old init cost ~12us inside the timed graph). sincospif is exact in the
// pi-scaling; argument x = t/8000 carries ~1ulp error -> twiddle error ~4e-7,
// far inside the 1e-3 budget.
#define N_INIT (NFFT + 100 + 10 + 5 + 50 + 500)

__global__ void init_tables_kernel() {
    int p = blockIdx.x * blockDim.x + threadIdx.x;
    float s, c;
    if (p < NFFT) {
        sincospif(-(float)p / 8000.0f, &s, &c);
        g_tw[p] = make_float2(c, s);
        return;
    }
    int q = p - NFFT;
    if (q < 100) {                       // g_twf1000[q] = cis(-2pi*16q/N) = cis(-pi*q/500)
        sincospif(-(float)q / 500.0f, &s, &c);
        g_twf1000[q] = make_float2(c, s);
        return;
    }
    q -= 100;
    if (q < 10) {                        // g_twf100[q] = cis(-pi*q/50)
        sincospif(-(float)q / 50.0f, &s, &c);
        g_twf100[q] = make_float2(c, s);
        return;
    }
    q -= 10;
    if (q < 5) {                         // g_twi50[q] = cis(+pi*q/25)
        sincospif((float)q / 25.0f, &s, &c);
        g_twi50[q] = make_float2(c, s);
        return;
    }
    q -= 5;
    if (q < 50) {                        // g_twi500[q] = cis(+pi*q/250)
        sincospif((float)q / 250.0f, &s, &c);
        g_twi500[q] = make_float2(c, s);
        return;
    }
    q -= 50;
    if (q < 500) {                       // g_twi8000[q] = cis(+pi*q/4000)
        sincospif((float)q / 4000.0f, &s, &c);
        g_twi8000[q] = make_float2(c, s);
    }
}

__device__ __forceinline__ int block_of(int f0) {
    return 100 * (f0 & 15) + 10 * ((f0 >> 4) % 10) + (f0 / 160);
}

__device__ __forceinline__ float2 cadd(float2 a, float2 b) { return make_float2(a.x + b.x, a.y + b.y); }
__device__ __forceinline__ float2 csub(float2 a, float2 b) { return make_float2(a.x - b.x, a.y - b.y); }
__device__ __forceinline__ float2 cmul(float2 a, float2 b) {
    return make_float2(fmaf(a.x, b.x, -a.y * b.y), fmaf(a.x, b.y, a.y * b.x));
}
__device__ __forceinline__ float2 cmulc(float2 a, float cr, float ci) {
    return make_float2(fmaf(a.x, cr, -a.y * ci), fmaf(a.x, ci, a.y * cr));
}
template <int DIR>
__device__ __forceinline__ float2 cmuli(float2 a) {   // * (DIR*i)
    return (DIR > 0) ? make_float2(-a.y, a.x) : make_float2(a.y, -a.x);
}

template <int DIR>
__device__ __forceinline__ void dft4(float2* x) {
    float2 t0 = cadd(x[0], x[2]);
    float2 t1 = csub(x[0], x[2]);
    float2 t2 = cadd(x[1], x[3]);
    float2 t3 = cmuli<DIR>(csub(x[1], x[3]));
    x[0] = cadd(t0, t2);
    x[2] = csub(t0, t2);
    x[1] = cadd(t1, t3);
    x[3] = csub(t1, t3);
}

template <int DIR>
__device__ __forceinline__ void dft5(float2* x) {
    const float c1 = 0.30901699437494742f;
    const float c2 = -0.80901699437494745f;
    const float s1 = 0.95105651629515357f;
    const float s2 = 0.58778525229247313f;
    float2 t1 = cadd(x[1], x[4]);
    float2 t2 = cadd(x[2], x[3]);
    float2 t3 = csub(x[1], x[4]);
    float2 t4 = csub(x[2], x[3]);
    float2 x0 = x[0];
    float2 a1 = make_float2(x0.x + c1 * t1.x + c2 * t2.x, x0.y + c1 * t1.y + c2 * t2.y);
    float2 a2 = make_float2(x0.x + c2 * t1.x + c1 * t2.x, x0.y + c2 * t1.y + c1 * t2.y);
    float2 b1 = make_float2(s1 * t3.x + s2 * t4.x, s1 * t3.y + s2 * t4.y);
    float2 b2 = make_float2(s2 * t3.x - s1 * t4.x, s2 * t3.y - s1 * t4.y);
    x[0] = make_float2(x0.x + t1.x + t2.x, x0.y + t1.y + t2.y);
    float2 ib1 = cmuli<DIR>(b1);
    float2 ib2 = cmuli<DIR>(b2);
    x[1] = cadd(a1, ib1);
    x[4] = csub(a1, ib1);
    x[2] = cadd(a2, ib2);
    x[3] = csub(a2, ib2);
}

// 10-point DFT = 2x5 CT, stride-S register access.
template <int DIR, int S>
__device__ __forceinline__ void dft10s(float2* x) {
    const float C36 = 0.80901699437494742f;
    const float S36 = 0.58778525229247313f;
    const float C72 = 0.30901699437494742f;
    const float S72 = 0.95105651629515357f;
    const float D = (float)DIR;
    float2 a[5], c[5];
#pragma unroll
    for (int k = 0; k < 5; k++) {
        a[k] = cadd(x[k * S], x[(k + 5) * S]);
        c[k] = csub(x[k * S], x[(k + 5) * S]);
    }
    c[1] = cmulc(c[1], C36, D * S36);
    c[2] = cmulc(c[2], C72, D * S72);
    c[3] = cmulc(c[3], -C72, D * S72);
    c[4] = cmulc(c[4], -C36, D * S36);
    dft5<DIR>(a);
    dft5<DIR>(c);
    x[0 * S] = a[0]; x[2 * S] = a[1]; x[4 * S] = a[2]; x[6 * S] = a[3]; x[8 * S] = a[4];
    x[1 * S] = c[0]; x[3 * S] = c[1]; x[5 * S] = c[2]; x[7 * S] = c[3]; x[9 * S] = c[4];
}

// 16-point DFT = 4x4 CT, stride-S register access.
template <int DIR, int S>
__device__ __forceinline__ void dft16s(float2* x) {
    const float C1 = 0.92387953251128674f;
    const float S1 = 0.38268343236508978f;
    const float C2 = 0.70710678118654752f;
    const float D = (float)DIR;
    float2 y[16];
#pragma unroll
    for (int n2 = 0; n2 < 4; n2++) {
        float2 t[4] = {x[n2 * S], x[(n2 + 4) * S], x[(n2 + 8) * S], x[(n2 + 12) * S]};
        dft4<DIR>(t);
        if (n2 == 1) {
            t[1] = cmulc(t[1], C1, D * S1);
            t[2] = cmulc(t[2], C2, D * C2);
            t[3] = cmulc(t[3], S1, D * C1);
        } else if (n2 == 2) {
            t[1] = cmulc(t[1], C2, D * C2);
            t[2] = cmuli<DIR>(t[2]);
            t[3] = cmulc(t[3], -C2, D * C2);
        } else if (n2 == 3) {
            t[1] = cmulc(t[1], S1, D * C1);
            t[2] = cmulc(t[2], -C2, D * C2);
            t[3] = cmulc(t[3], -C1, -D * S1);
        }
        y[0 + n2] = t[0]; y[4 + n2] = t[1]; y[8 + n2] = t[2]; y[12 + n2] = t[3];
    }
#pragma unroll
    for (int k1 = 0; k1 < 4; k1++) {
        float2 t[4] = {y[k1 * 4 + 0], y[k1 * 4 + 1], y[k1 * 4 + 2], y[k1 * 4 + 3]};
        dft4<DIR>(t);
        x[(k1 + 0) * S] = t[0]; x[(k1 + 4) * S] = t[1];
        x[(k1 + 8) * S] = t[2]; x[(k1 + 12) * S] = t[3];
    }
}

// Twiddle application: odd/even accumulator chains stepping by w^2.
template <int S>
__device__ __forceinline__ void apply_tw10_chain(float2* x, float2 w1) {
    float2 w2 = cmul(w1, w1);
    float2 wo = w1, we = w2;
    x[1 * S] = cmul(x[1 * S], wo);
    x[2 * S] = cmul(x[2 * S], we);
#pragma unroll
    for (int j = 3; j < 10; j += 2) {
        wo = cmul(wo, w2); x[j * S] = cmul(x[j * S], wo);
        if (j + 1 < 10) { we = cmul(we, w2); x[(j + 1) * S] = cmul(x[(j + 1) * S], we); }
    }
}

template <int S>
__device__ __forceinline__ void apply_tw16_chain(float2* x, float2 w1) {
    float2 w2 = cmul(w1, w1);
    float2 wo = w1, we = w2;
    x[1 * S] = cmul(x[1 * S], wo);
    x[2 * S] = cmul(x[2 * S], we);
#pragma unroll
    for (int j = 3; j < 16; j += 2) {
        wo = cmul(wo, w2); x[j * S] = cmul(x[j * S], wo);
        if (j + 1 < 16) { we = cmul(we, w2); x[(j + 1) * S] = cmul(x[(j + 1) * S], we); }
    }
}

// Forward radix-16 stage (NS=16000, m=1000), DIF, paired via float4.
__device__ __forceinline__ void stage16_fwd(float2* sm, int tid) {
    if (tid >= 500) return;
    int n2 = 2 * tid;
    float2 X[32];   // even slots: butterfly A (n2), odd: butterfly B (n2+1)
#pragma unroll
    for (int j = 0; j < 16; j++) {
        float4 t = *(const float4*)&sm[PHI(n2 + j * 1000)];
        X[2 * j]     = make_float2(t.x, t.y);
        X[2 * j + 1] = make_float2(t.z, t.w);
    }
    dft16s<-1, 2>(X);
    dft16s<-1, 2>(X + 1);
    float4 wv = *(const float4*)&g_tw[n2];
    apply_tw16_chain<2>(X, make_float2(wv.x, wv.y));
    apply_tw16_chain<2>(X + 1, make_float2(wv.z, wv.w));
#pragma unroll
    for (int j = 0; j < 16; j++) {
        *(float4*)&sm[PHI(n2 + j * 1000)] =
            make_float4(X[2 * j].x, X[2 * j].y, X[2 * j + 1].x, X[2 * j + 1].y);
    }
}

// Forward radix-10 stage, two adjacent butterflies per thread; 800 tasks = BT.
template <int NS>
__device__ __forceinline__ void stage10_paired(float2* sm, int tid, const float2* __restrict__ tab) {
    constexpr int m = NS / 10;
    constexpr int halfm = m / 2;
    int blk = tid / halfm;
    int h = tid - blk * halfm;
    int n2 = 2 * h;
    int base = blk * NS + n2;
    float2 X[20];
#pragma unroll
    for (int j = 0; j < 10; j++) {
        float4 t = *(const float4*)&sm[PHI(base + j * m)];
        X[2 * j]     = make_float2(t.x, t.y);
        X[2 * j + 1] = make_float2(t.z, t.w);
    }
    float4 wv = *(const float4*)&tab[n2];
    dft10s<-1, 2>(X);
    apply_tw10_chain<2>(X, make_float2(wv.x, wv.y));
    dft10s<-1, 2>(X + 1);
    apply_tw10_chain<2>(X + 1, make_float2(wv.z, wv.w));
#pragma unroll
    for (int j = 0; j < 10; j++) {
        *(float4*)&sm[PHI(base + j * m)] =
            make_float4(X[2 * j].x, X[2 * j].y, X[2 * j + 1].x, X[2 * j + 1].y);
    }
}

// Inverse (DIT) stage on the 8000-point array; w1 from pre-conjugated coalesced table.
template <int R, int NS, bool TO_GMEM>
__device__ __forceinline__ void stage8_inv(float2* s8, int tid, float2* __restrict__ gout2,
                                           const float2* __restrict__ tab) {
    constexpr int m = NS / R;
    constexpr int nb = NH / R;
    for (int u = tid; u < nb; u += BT) {
        int blk = u / m;
        int n2 = u - blk * m;
        int base = blk * NS + n2;
        float2 x[R];
#pragma unroll
        for (int j = 0; j < R; j++) x[j] = s8[PHI8(base + j * m)];
        float2 w1 = tab[n2];
        if constexpr (R == 16) {
            apply_tw16_chain<1>(x, w1);
            dft16s<1, 1>(x);
        } else {
            apply_tw10_chain<1>(x, w1);
            dft10s<1, 1>(x);
        }
#pragma unroll
        for (int j = 0; j < R; j++) {
            if constexpr (TO_GMEM) gout2[base + j * m] = x[j];   // c[n] -> (z[2n], z[2n+1])
            else s8[PHI8(base + j * m)] = x[j];
        }
    }
}

__device__ __forceinline__ void pw(float2& A, float2& C, float scale) {
    float2 a = A, c = C;
    float2 Fi = make_float2(a.x + c.x, a.y - c.y);
    float2 Fs = make_float2(a.y + c.y, -(a.x - c.x));
    float2 Z = cmul(Fi, Fs);
    Z.x *= scale; Z.y *= scale;
    A = Z;
    C = make_float2(Z.x, -Z.y);
}

// Pack Z-block (10 values, f = f0+1600t) into 5 C values of the 8000-domain,
// then first inverse stage (radix-5), store at s8[PHI8(5b + j)].
__device__ __forceinline__ void pack_inv5_store(const float2* x, float2 w0,
                                                float2* s8, int b) {
    const float RC[5] = {1.f, 0.80901699437494742f, 0.30901699437494742f,
                         -0.30901699437494742f, -0.80901699437494742f};
    const float RS[5] = {0.f, 0.58778525229247313f, 0.95105651629515357f,
                         0.95105651629515357f, 0.58778525229247313f};
    float2 C[5];
#pragma unroll
    for (int t = 0; t < 5; t++) {
        float2 S = cadd(x[t], x[t + 5]);
        float2 Dd = csub(x[t], x[t + 5]);
        float2 wt = (t == 0) ? w0 : cmul(w0, make_float2(RC[t], RS[t]));
        C[t] = cadd(S, cmuli<1>(cmul(wt, Dd)));
    }
    dft5<1>(C);
    int base = PHI8(5 * b);   // 5b..5b+4 never cross a 50-group
#pragma unroll
    for (int j = 0; j < 5; j++) s8[base + j] = C[j];
}

// Fused middle: forward radix-10 (m=1) + Hermitian pointwise + pack + inverse radix-5.
__device__ __forceinline__ void fused_mid(float2* sm, float2* s8, int tid) {
    const float scale = 0.25f / (float)NFFT;
    int fa, fb;
    if (tid < 799) { fa = tid + 1; fb = 1600 - fa; }
    else           { fa = 0;       fb = 800; }
    int b  = block_of(fa);
    int b2 = block_of(fb);
    int pa = PHI(10 * b);
    int pb = PHI(10 * b2);
    float2 xa[10], xb[10];
#pragma unroll
    for (int k = 0; k < 5; k++) {
        float4 t = *(const float4*)&sm[pa + 2 * k];
        xa[2 * k] = make_float2(t.x, t.y); xa[2 * k + 1] = make_float2(t.z, t.w);
        float4 s = *(const float4*)&sm[pb + 2 * k];
        xb[2 * k] = make_float2(s.x, s.y); xb[2 * k + 1] = make_float2(s.z, s.w);
    }
    dft10s<-1, 1>(xa);
    dft10s<-1, 1>(xb);
    if (tid < 799) {
#pragma unroll
        for (int t = 0; t < 10; t++) pw(xa[t], xb[9 - t], scale);
    } else {
        pw(xa[0], xa[0], scale);
        pw(xa[5], xa[5], scale);
        pw(xa[1], xa[9], scale);
        pw(xa[2], xa[8], scale);
        pw(xa[3], xa[7], scale);
        pw(xa[4], xa[6], scale);
        pw(xb[0], xb[9], scale);
        pw(xb[1], xb[8], scale);
        pw(xb[2], xb[7], scale);
        pw(xb[3], xb[6], scale);
        pw(xb[4], xb[5], scale);
    }
    float2 ta = g_tw[fa]; ta.y = -ta.y;   // e^{+2pi i fa/16000}, coalesced (fa=tid+1)
    float2 tb = g_tw[fb]; tb.y = -tb.y;
    pack_inv5_store(xa, ta, s8, b);
    pack_inv5_store(xb, tb, s8, b2);
}

__global__ void __launch_bounds__(BT) mcb_main_kernel(
    const float* __restrict__ img, const float* __restrict__ seq,
    const int* __restrict__ hv, const float* __restrict__ sv,
    float* __restrict__ out, int d) {
    extern __shared__ float2 sm[];
    float2* s8 = sm + SMPAD;
    const int b = blockIdx.x;
    const int tid = threadIdx.x;

    float4* sm4 = (float4*)sm;
    for (int i = tid; i < SMPAD / 2; i += BT) sm4[i] = make_float4(0.f, 0.f, 0.f, 0.f);
    __syncthreads();

    const float* irow = img + (size_t)b * d;
    const float* qrow = seq + (size_t)b * d;
    for (int i = tid; i < d; i += BT) {
        int h = PHI(hv[i]);
        float s = sv[i];
        atomicAdd(&sm[h].x, irow[i] * s);
        atomicAdd(&sm[h].y, qrow[i] * s);
    }
    __syncthreads();

    float2* orow2 = (float2*)(out + (size_t)b * NFFT);

    // forward 16000: 16 (paired), 10, 10 | fused(10 + pointwise + pack + inv5)
    stage16_fwd(sm, tid);                        __syncthreads();
    stage10_paired<1000>(sm, tid, g_twf1000);    __syncthreads();
    stage10_paired<100>(sm, tid, g_twf100);      __syncthreads();
    fused_mid(sm, s8, tid);                      __syncthreads();
    // inverse 8000: 10 (m=5), 10 (m=50), 16 (m=500) -> gmem float2
    stage8_inv<10, 50, false>(s8, tid, orow2, g_twi50);     __syncthreads();
    stage8_inv<10, 500, false>(s8, tid, orow2, g_twi500);   __syncthreads();
    stage8_inv<16, 8000, true>(s8, tid, orow2, g_twi8000);
}

extern "C" void kernel_launch(void* const* d_in, const int* in_sizes, int n_in,
                              void* d_out, int out_size) {
    const float* img = (const float*)d_in[0];
    const float* seq = (const float*)d_in[1];
    const int* hv = (const int*)d_in[2];
    const float* sv = (const float*)d_in[3];
    float* out = (float*)d_out;

    int d = in_sizes[2];
    int B = in_sizes[0] / d;

    static_assert(NFFT == 16000 && NH == 8000, "plan assumes N=16000");

    cudaFuncSetAttribute(mcb_main_kernel, cudaFuncAttributeMaxDynamicSharedMemorySize,
                         SMTOTAL);

    init_tables_kernel<<<(N_INIT + 255) / 256, 256>>>();
    mcb_main_kernel<<<B, BT, SMTOTAL>>>(img, seq, hv, sv, out, d);
}

// round 14
// speedup vs baseline: 1.2049x; 1.0333x over previous
#include <cuda_runtime.h>

#define NFFT 16000
#define NH   8000
#define BT   800
// 16000-domain padding (forward stages)
#define PHI(i)  ((i) + 6 * ((i) / 100))
#define SMPAD   (NFFT + 6 * (NFFT / 100))        // 16960 float2
// 8000-domain padding (inverse stages), separate region
#define PHI8(i) ((i) + 3 * ((i) / 50))
#define SMPAD8  (NH + 3 * (NH / 50))             // 8480 float2
#define SMTOTAL ((SMPAD + SMPAD8) * sizeof(float2))  // 203,520 B

// Forward plan (DIF) on 16000: 16,10,10,10 -> strides 1000,100,10,1
// Inverse plan (DIT) on 8000:  [16,10,10,5]; digit maps as in earlier rounds.

__device__ __align__(16) float2 g_tw[NFFT];      // e^{-2*pi*i*t/16000}
__device__ __align__(16) float2 g_twf1000[100];  // g_tw[16*n2]
__device__ __align__(16) float2 g_twf100[16];    // g_tw[160*n2]
__device__ __align__(16) float2 g_twi50[8];      // conj g_tw[320*n2]
__device__ __align__(16) float2 g_twi500[56];    // conj g_tw[32*n2]
__device__ __align__(16) float2 g_twi8000[500];  // conj g_tw[2*n2]

// Flat init: ONE sincospif per thread (fp32, pi-exact scaling) — keeps the
// init kernel ~1us inside the timed graph (the fp64 version cost ~12us).
#define N_INIT (NFFT + 100 + 10 + 5 + 50 + 500)

__global__ void init_tables_kernel() {
    int p = blockIdx.x * blockDim.x + threadIdx.x;
    float s, c;
    if (p < NFFT) {
        sincospif(-(float)p / 8000.0f, &s, &c);
        g_tw[p] = make_float2(c, s);
        return;
    }
    int q = p - NFFT;
    if (q < 100) {                       // g_twf1000[q] = cis(-pi*q/500)
        sincospif(-(float)q / 500.0f, &s, &c);
        g_twf1000[q] = make_float2(c, s);
        return;
    }
    q -= 100;
    if (q < 10) {                        // g_twf100[q] = cis(-pi*q/50)
        sincospif(-(float)q / 50.0f, &s, &c);
        g_twf100[q] = make_float2(c, s);
        return;
    }
    q -= 10;
    if (q < 5) {                         // g_twi50[q] = cis(+pi*q/25)
        sincospif((float)q / 25.0f, &s, &c);
        g_twi50[q] = make_float2(c, s);
        return;
    }
    q -= 5;
    if (q < 50) {                        // g_twi500[q] = cis(+pi*q/250)
        sincospif((float)q / 250.0f, &s, &c);
        g_twi500[q] = make_float2(c, s);
        return;
    }
    q -= 50;
    if (q < 500) {                       // g_twi8000[q] = cis(+pi*q/4000)
        sincospif((float)q / 4000.0f, &s, &c);
        g_twi8000[q] = make_float2(c, s);
    }
}

__device__ __forceinline__ int block_of(int f0) {
    return 100 * (f0 & 15) + 10 * ((f0 >> 4) % 10) + (f0 / 160);
}

__device__ __forceinline__ float2 cadd(float2 a, float2 b) { return make_float2(a.x + b.x, a.y + b.y); }
__device__ __forceinline__ float2 csub(float2 a, float2 b) { return make_float2(a.x - b.x, a.y - b.y); }
__device__ __forceinline__ float2 cmul(float2 a, float2 b) {
    return make_float2(fmaf(a.x, b.x, -a.y * b.y), fmaf(a.x, b.y, a.y * b.x));
}
__device__ __forceinline__ float2 cmulc(float2 a, float cr, float ci) {
    return make_float2(fmaf(a.x, cr, -a.y * ci), fmaf(a.x, ci, a.y * cr));
}
template <int DIR>
__device__ __forceinline__ float2 cmuli(float2 a) {   // * (DIR*i)
    return (DIR > 0) ? make_float2(-a.y, a.x) : make_float2(a.y, -a.x);
}

template <int DIR>
__device__ __forceinline__ void dft4(float2* x) {
    float2 t0 = cadd(x[0], x[2]);
    float2 t1 = csub(x[0], x[2]);
    float2 t2 = cadd(x[1], x[3]);
    float2 t3 = cmuli<DIR>(csub(x[1], x[3]));
    x[0] = cadd(t0, t2);
    x[2] = csub(t0, t2);
    x[1] = cadd(t1, t3);
    x[3] = csub(t1, t3);
}

template <int DIR>
__device__ __forceinline__ void dft5(float2* x) {
    const float c1 = 0.30901699437494742f;
    const float c2 = -0.80901699437494745f;
    const float s1 = 0.95105651629515357f;
    const float s2 = 0.58778525229247313f;
    float2 t1 = cadd(x[1], x[4]);
    float2 t2 = cadd(x[2], x[3]);
    float2 t3 = csub(x[1], x[4]);
    float2 t4 = csub(x[2], x[3]);
    float2 x0 = x[0];
    float2 a1 = make_float2(x0.x + c1 * t1.x + c2 * t2.x, x0.y + c1 * t1.y + c2 * t2.y);
    float2 a2 = make_float2(x0.x + c2 * t1.x + c1 * t2.x, x0.y + c2 * t1.y + c1 * t2.y);
    float2 b1 = make_float2(s1 * t3.x + s2 * t4.x, s1 * t3.y + s2 * t4.y);
    float2 b2 = make_float2(s2 * t3.x - s1 * t4.x, s2 * t3.y - s1 * t4.y);
    x[0] = make_float2(x0.x + t1.x + t2.x, x0.y + t1.y + t2.y);
    float2 ib1 = cmuli<DIR>(b1);
    float2 ib2 = cmuli<DIR>(b2);
    x[1] = cadd(a1, ib1);
    x[4] = csub(a1, ib1);
    x[2] = cadd(a2, ib2);
    x[3] = csub(a2, ib2);
}

// 10-point DFT = 2x5 CT, stride-S register access.
template <int DIR, int S>
__device__ __forceinline__ void dft10s(float2* x) {
    const float C36 = 0.80901699437494742f;
    const float S36 = 0.58778525229247313f;
    const float C72 = 0.30901699437494742f;
    const float S72 = 0.95105651629515357f;
    const float D = (float)DIR;
    float2 a[5], c[5];
#pragma unroll
    for (int k = 0; k < 5; k++) {
        a[k] = cadd(x[k * S], x[(k + 5) * S]);
        c[k] = csub(x[k * S], x[(k + 5) * S]);
    }
    c[1] = cmulc(c[1], C36, D * S36);
    c[2] = cmulc(c[2], C72, D * S72);
    c[3] = cmulc(c[3], -C72, D * S72);
    c[4] = cmulc(c[4], -C36, D * S36);
    dft5<DIR>(a);
    dft5<DIR>(c);
    x[0 * S] = a[0]; x[2 * S] = a[1]; x[4 * S] = a[2]; x[6 * S] = a[3]; x[8 * S] = a[4];
    x[1 * S] = c[0]; x[3 * S] = c[1]; x[5 * S] = c[2]; x[7 * S] = c[3]; x[9 * S] = c[4];
}

// 16-point DFT = 4x4 CT, stride-S register access.
template <int DIR, int S>
__device__ __forceinline__ void dft16s(float2* x) {
    const float C1 = 0.92387953251128674f;
    const float S1 = 0.38268343236508978f;
    const float C2 = 0.70710678118654752f;
    const float D = (float)DIR;
    float2 y[16];
#pragma unroll
    for (int n2 = 0; n2 < 4; n2++) {
        float2 t[4] = {x[n2 * S], x[(n2 + 4) * S], x[(n2 + 8) * S], x[(n2 + 12) * S]};
        dft4<DIR>(t);
        if (n2 == 1) {
            t[1] = cmulc(t[1], C1, D * S1);
            t[2] = cmulc(t[2], C2, D * C2);
            t[3] = cmulc(t[3], S1, D * C1);
        } else if (n2 == 2) {
            t[1] = cmulc(t[1], C2, D * C2);
            t[2] = cmuli<DIR>(t[2]);
            t[3] = cmulc(t[3], -C2, D * C2);
        } else if (n2 == 3) {
            t[1] = cmulc(t[1], S1, D * C1);
            t[2] = cmulc(t[2], -C2, D * C2);
            t[3] = cmulc(t[3], -C1, -D * S1);
        }
        y[0 + n2] = t[0]; y[4 + n2] = t[1]; y[8 + n2] = t[2]; y[12 + n2] = t[3];
    }
#pragma unroll
    for (int k1 = 0; k1 < 4; k1++) {
        float2 t[4] = {y[k1 * 4 + 0], y[k1 * 4 + 1], y[k1 * 4 + 2], y[k1 * 4 + 3]};
        dft4<DIR>(t);
        x[(k1 + 0) * S] = t[0]; x[(k1 + 4) * S] = t[1];
        x[(k1 + 8) * S] = t[2]; x[(k1 + 12) * S] = t[3];
    }
}

// Twiddle application: odd/even accumulator chains stepping by w^2.
template <int S>
__device__ __forceinline__ void apply_tw10_chain(float2* x, float2 w1) {
    float2 w2 = cmul(w1, w1);
    float2 wo = w1, we = w2;
    x[1 * S] = cmul(x[1 * S], wo);
    x[2 * S] = cmul(x[2 * S], we);
#pragma unroll
    for (int j = 3; j < 10; j += 2) {
        wo = cmul(wo, w2); x[j * S] = cmul(x[j * S], wo);
        if (j + 1 < 10) { we = cmul(we, w2); x[(j + 1) * S] = cmul(x[(j + 1) * S], we); }
    }
}

template <int S>
__device__ __forceinline__ void apply_tw16_chain(float2* x, float2 w1) {
    float2 w2 = cmul(w1, w1);
    float2 wo = w1, we = w2;
    x[1 * S] = cmul(x[1 * S], wo);
    x[2 * S] = cmul(x[2 * S], we);
#pragma unroll
    for (int j = 3; j < 16; j += 2) {
        wo = cmul(wo, w2); x[j * S] = cmul(x[j * S], wo);
        if (j + 1 < 16) { we = cmul(we, w2); x[(j + 1) * S] = cmul(x[(j + 1) * S], we); }
    }
}

// Forward radix-16 stage (NS=16000, m=1000), DIF, paired via float4.
__device__ __forceinline__ void stage16_fwd(float2* sm, int tid) {
    if (tid >= 500) return;
    int n2 = 2 * tid;
    float2 X[32];   // even slots: butterfly A (n2), odd: butterfly B (n2+1)
#pragma unroll
    for (int j = 0; j < 16; j++) {
        float4 t = *(const float4*)&sm[PHI(n2 + j * 1000)];
        X[2 * j]     = make_float2(t.x, t.y);
        X[2 * j + 1] = make_float2(t.z, t.w);
    }
    dft16s<-1, 2>(X);
    dft16s<-1, 2>(X + 1);
    float4 wv = *(const float4*)&g_tw[n2];
    apply_tw16_chain<2>(X, make_float2(wv.x, wv.y));
    apply_tw16_chain<2>(X + 1, make_float2(wv.z, wv.w));
#pragma unroll
    for (int j = 0; j < 16; j++) {
        *(float4*)&sm[PHI(n2 + j * 1000)] =
            make_float4(X[2 * j].x, X[2 * j].y, X[2 * j + 1].x, X[2 * j + 1].y);
    }
}

// Forward radix-10 stage, two adjacent butterflies per thread; 800 tasks = BT.
template <int NS>
__device__ __forceinline__ void stage10_paired(float2* sm, int tid, const float2* __restrict__ tab) {
    constexpr int m = NS / 10;
    constexpr int halfm = m / 2;
    int blk = tid / halfm;
    int h = tid - blk * halfm;
    int n2 = 2 * h;
    int base = blk * NS + n2;
    float2 X[20];
#pragma unroll
    for (int j = 0; j < 10; j++) {
        float4 t = *(const float4*)&sm[PHI(base + j * m)];
        X[2 * j]     = make_float2(t.x, t.y);
        X[2 * j + 1] = make_float2(t.z, t.w);
    }
    float4 wv = *(const float4*)&tab[n2];
    dft10s<-1, 2>(X);
    apply_tw10_chain<2>(X, make_float2(wv.x, wv.y));
    dft10s<-1, 2>(X + 1);
    apply_tw10_chain<2>(X + 1, make_float2(wv.z, wv.w));
#pragma unroll
    for (int j = 0; j < 10; j++) {
        *(float4*)&sm[PHI(base + j * m)] =
            make_float4(X[2 * j].x, X[2 * j].y, X[2 * j + 1].x, X[2 * j + 1].y);
    }
}

// Inverse (DIT) stage on the 8000-point array; w1 from pre-conjugated coalesced table.
template <int R, int NS, bool TO_GMEM>
__device__ __forceinline__ void stage8_inv(float2* s8, int tid, float2* __restrict__ gout2,
                                           const float2* __restrict__ tab) {
    constexpr int m = NS / R;
    constexpr int nb = NH / R;
    for (int u = tid; u < nb; u += BT) {
        int blk = u / m;
        int n2 = u - blk * m;
        int base = blk * NS + n2;
        float2 x[R];
#pragma unroll
        for (int j = 0; j < R; j++) x[j] = s8[PHI8(base + j * m)];
        float2 w1 = tab[n2];
        if constexpr (R == 16) {
            apply_tw16_chain<1>(x, w1);
            dft16s<1, 1>(x);
        } else {
            apply_tw10_chain<1>(x, w1);
            dft10s<1, 1>(x);
        }
#pragma unroll
        for (int j = 0; j < R; j++) {
            if constexpr (TO_GMEM) gout2[base + j * m] = x[j];   // c[n] -> (z[2n], z[2n+1])
            else s8[PHI8(base + j * m)] = x[j];
        }
    }
}

__device__ __forceinline__ void pw(float2& A, float2& C, float scale) {
    float2 a = A, c = C;
    float2 Fi = make_float2(a.x + c.x, a.y - c.y);
    float2 Fs = make_float2(a.y + c.y, -(a.x - c.x));
    float2 Z = cmul(Fi, Fs);
    Z.x *= scale; Z.y *= scale;
    A = Z;
    C = make_float2(Z.x, -Z.y);
}

// Pack Z-block (10 values, f = f0+1600t) into 5 C values of the 8000-domain,
// then first inverse stage (radix-5), store at s8[PHI8(5b + j)].
__device__ __forceinline__ void pack_inv5_store(const float2* x, float2 w0,
                                                float2* s8, int b) {
    const float RC[5] = {1.f, 0.80901699437494742f, 0.30901699437494742f,
                         -0.30901699437494742f, -0.80901699437494742f};
    const float RS[5] = {0.f, 0.58778525229247313f, 0.95105651629515357f,
                         0.95105651629515357f, 0.58778525229247313f};
    float2 C[5];
#pragma unroll
    for (int t = 0; t < 5; t++) {
        float2 S = cadd(x[t], x[t + 5]);
        float2 Dd = csub(x[t], x[t + 5]);
        float2 wt = (t == 0) ? w0 : cmul(w0, make_float2(RC[t], RS[t]));
        C[t] = cadd(S, cmuli<1>(cmul(wt, Dd)));
    }
    dft5<1>(C);
    int base = PHI8(5 * b);   // 5b..5b+4 never cross a 50-group
#pragma unroll
    for (int j = 0; j < 5; j++) s8[base + j] = C[j];
}

// Fused middle: forward radix-10 (m=1) + Hermitian pointwise + pack + inverse radix-5.
__device__ __forceinline__ void fused_mid(float2* sm, float2* s8, int tid) {
    const float scale = 0.25f / (float)NFFT;
    int fa, fb;
    if (tid < 799) { fa = tid + 1; fb = 1600 - fa; }
    else           { fa = 0;       fb = 800; }
    int b  = block_of(fa);
    int b2 = block_of(fb);
    int pa = PHI(10 * b);
    int pb = PHI(10 * b2);
    float2 xa[10], xb[10];
#pragma unroll
    for (int k = 0; k < 5; k++) {
        float4 t = *(const float4*)&sm[pa + 2 * k];
        xa[2 * k] = make_float2(t.x, t.y); xa[2 * k + 1] = make_float2(t.z, t.w);
        float4 s = *(const float4*)&sm[pb + 2 * k];
        xb[2 * k] = make_float2(s.x, s.y); xb[2 * k + 1] = make_float2(s.z, s.w);
    }
    dft10s<-1, 1>(xa);
    dft10s<-1, 1>(xb);
    if (tid < 799) {
#pragma unroll
        for (int t = 0; t < 10; t++) pw(xa[t], xb[9 - t], scale);
    } else {
        pw(xa[0], xa[0], scale);
        pw(xa[5], xa[5], scale);
        pw(xa[1], xa[9], scale);
        pw(xa[2], xa[8], scale);
        pw(xa[3], xa[7], scale);
        pw(xa[4], xa[6], scale);
        pw(xb[0], xb[9], scale);
        pw(xb[1], xb[8], scale);
        pw(xb[2], xb[7], scale);
        pw(xb[3], xb[6], scale);
        pw(xb[4], xb[5], scale);
    }
    float2 ta = g_tw[fa]; ta.y = -ta.y;   // e^{+2pi i fa/16000}, coalesced (fa=tid+1)
    float2 tb = g_tw[fb]; tb.y = -tb.y;
    pack_inv5_store(xa, ta, s8, b);
    pack_inv5_store(xb, tb, s8, b2);
}

__global__ void __launch_bounds__(BT) mcb_main_kernel(
    const float* __restrict__ img, const float* __restrict__ seq,
    const int* __restrict__ hv, const float* __restrict__ sv,
    float* __restrict__ out, int d) {
    extern __shared__ float2 sm[];
    float2* s8 = sm + SMPAD;
    const int b = blockIdx.x;
    const int tid = threadIdx.x;

    float4* sm4 = (float4*)sm;
    for (int i = tid; i < SMPAD / 2; i += BT) sm4[i] = make_float4(0.f, 0.f, 0.f, 0.f);
    __syncthreads();

    // vectorized scatter: two features per iteration (int2/float2 loads;
    // all row bases are 8B-aligned: row stride = d floats, d even).
    {
        const int P = d >> 1;   // feature pairs
        const int2*   hv2 = (const int2*)hv;
        const float2* sv2 = (const float2*)sv;
        const float2* im2 = (const float2*)(img + (size_t)b * d);
        const float2* sq2 = (const float2*)(seq + (size_t)b * d);
        for (int i = tid; i < P; i += BT) {
            int2   h2 = hv2[i];
            float2 s2 = sv2[i];
            float2 a2 = im2[i];
            float2 q2 = sq2[i];
            int ha = PHI(h2.x);
            int hb = PHI(h2.y);
            atomicAdd(&sm[ha].x, a2.x * s2.x);
            atomicAdd(&sm[ha].y, q2.x * s2.x);
            atomicAdd(&sm[hb].x, a2.y * s2.y);
            atomicAdd(&sm[hb].y, q2.y * s2.y);
        }
    }
    __syncthreads();

    float2* orow2 = (float2*)(out + (size_t)b * NFFT);

    // forward 16000: 16 (paired), 10, 10 | fused(10 + pointwise + pack + inv5)
    stage16_fwd(sm, tid);                        __syncthreads();
    stage10_paired<1000>(sm, tid, g_twf1000);    __syncthreads();
    stage10_paired<100>(sm, tid, g_twf100);      __syncthreads();
    fused_mid(sm, s8, tid);                      __syncthreads();
    // inverse 8000: 10 (m=5), 10 (m=50), 16 (m=500) -> gmem float2
    stage8_inv<10, 50, false>(s8, tid, orow2, g_twi50);     __syncthreads();
    stage8_inv<10, 500, false>(s8, tid, orow2, g_twi500);   __syncthreads();
    stage8_inv<16, 8000, true>(s8, tid, orow2, g_twi8000);
}

extern "C" void kernel_launch(void* const* d_in, const int* in_sizes, int n_in,
                              void* d_out, int out_size) {
    const float* img = (const float*)d_in[0];
    const float* seq = (const float*)d_in[1];
    const int* hv = (const int*)d_in[2];
    const float* sv = (const float*)d_in[3];
    float* out = (float*)d_out;

    int d = in_sizes[2];
    int B = in_sizes[0] / d;

    static_assert(NFFT == 16000 && NH == 8000, "plan assumes N=16000");

    cudaFuncSetAttribute(mcb_main_kernel, cudaFuncAttributeMaxDynamicSharedMemorySize,
                         SMTOTAL);

    init_tables_kernel<<<(N_INIT + 255) / 256, 256>>>();
    mcb_main_kernel<<<B, BT, SMTOTAL>>>(img, seq, hv, sv, out, d);
}

// round 15
// speedup vs baseline: 1.2897x; 1.0704x over previous
#include <cuda_runtime.h>

#define NFFT 16000
#define NH   8000
#define BT   800
// 16000-domain padding (forward stages)
#define PHI(i)  ((i) + 6 * ((i) / 100))
#define SMPAD   (NFFT + 6 * (NFFT / 100))        // 16960 float2
// 8000-domain padding (inverse stages), separate region
#define PHI8(i) ((i) + 3 * ((i) / 50))
#define SMPAD8  (NH + 3 * (NH / 50))             // 8480 float2
#define SMTOTAL ((SMPAD + SMPAD8) * sizeof(float2))  // 203,520 B

// Forward plan (DIF) on 16000: 16,10,10,10 -> strides 1000,100,10,1
// Inverse plan (DIT) on 8000:  [16,10,10,5]; digit maps as in earlier rounds.

__device__ __align__(16) float2 g_tw[NFFT];      // e^{-2*pi*i*t/16000}
__device__ __align__(16) float2 g_twf1000[100];  // g_tw[16*n2]
__device__ __align__(16) float2 g_twf100[16];    // g_tw[160*n2]
__device__ __align__(16) float2 g_twi50[8];      // conj g_tw[320*n2]
__device__ __align__(16) float2 g_twi500[56];    // conj g_tw[32*n2]
__device__ __align__(16) float2 g_twi8000[500];  // conj g_tw[2*n2]

// Flat init: ONE sincospif per thread (fp32, pi-exact scaling) — keeps the
// init kernel ~1us inside the timed graph (the fp64 version cost ~12us).
#define N_INIT (NFFT + 100 + 10 + 5 + 50 + 500)

__global__ void init_tables_kernel() {
    int p = blockIdx.x * blockDim.x + threadIdx.x;
    float s, c;
    if (p < NFFT) {
        sincospif(-(float)p / 8000.0f, &s, &c);
        g_tw[p] = make_float2(c, s);
        return;
    }
    int q = p - NFFT;
    if (q < 100) {                       // g_twf1000[q] = cis(-pi*q/500)
        sincospif(-(float)q / 500.0f, &s, &c);
        g_twf1000[q] = make_float2(c, s);
        return;
    }
    q -= 100;
    if (q < 10) {                        // g_twf100[q] = cis(-pi*q/50)
        sincospif(-(float)q / 50.0f, &s, &c);
        g_twf100[q] = make_float2(c, s);
        return;
    }
    q -= 10;
    if (q < 5) {                         // g_twi50[q] = cis(+pi*q/25)
        sincospif((float)q / 25.0f, &s, &c);
        g_twi50[q] = make_float2(c, s);
        return;
    }
    q -= 5;
    if (q < 50) {                        // g_twi500[q] = cis(+pi*q/250)
        sincospif((float)q / 250.0f, &s, &c);
        g_twi500[q] = make_float2(c, s);
        return;
    }
    q -= 50;
    if (q < 500) {                       // g_twi8000[q] = cis(+pi*q/4000)
        sincospif((float)q / 4000.0f, &s, &c);
        g_twi8000[q] = make_float2(c, s);
    }
}

__device__ __forceinline__ int block_of(int f0) {
    return 100 * (f0 & 15) + 10 * ((f0 >> 4) % 10) + (f0 / 160);
}

__device__ __forceinline__ float2 cadd(float2 a, float2 b) { return make_float2(a.x + b.x, a.y + b.y); }
__device__ __forceinline__ float2 csub(float2 a, float2 b) { return make_float2(a.x - b.x, a.y - b.y); }
__device__ __forceinline__ float2 cmul(float2 a, float2 b) {
    return make_float2(fmaf(a.x, b.x, -a.y * b.y), fmaf(a.x, b.y, a.y * b.x));
}
__device__ __forceinline__ float2 cmulc(float2 a, float cr, float ci) {
    return make_float2(fmaf(a.x, cr, -a.y * ci), fmaf(a.x, ci, a.y * cr));
}
template <int DIR>
__device__ __forceinline__ float2 cmuli(float2 a) {   // * (DIR*i)
    return (DIR > 0) ? make_float2(-a.y, a.x) : make_float2(a.y, -a.x);
}

template <int DIR>
__device__ __forceinline__ void dft4(float2* x) {
    float2 t0 = cadd(x[0], x[2]);
    float2 t1 = csub(x[0], x[2]);
    float2 t2 = cadd(x[1], x[3]);
    float2 t3 = cmuli<DIR>(csub(x[1], x[3]));
    x[0] = cadd(t0, t2);
    x[2] = csub(t0, t2);
    x[1] = cadd(t1, t3);
    x[3] = csub(t1, t3);
}

template <int DIR>
__device__ __forceinline__ void dft5(float2* x) {
    const float c1 = 0.30901699437494742f;
    const float c2 = -0.80901699437494745f;
    const float s1 = 0.95105651629515357f;
    const float s2 = 0.58778525229247313f;
    float2 t1 = cadd(x[1], x[4]);
    float2 t2 = cadd(x[2], x[3]);
    float2 t3 = csub(x[1], x[4]);
    float2 t4 = csub(x[2], x[3]);
    float2 x0 = x[0];
    float2 a1 = make_float2(x0.x + c1 * t1.x + c2 * t2.x, x0.y + c1 * t1.y + c2 * t2.y);
    float2 a2 = make_float2(x0.x + c2 * t1.x + c1 * t2.x, x0.y + c2 * t1.y + c1 * t2.y);
    float2 b1 = make_float2(s1 * t3.x + s2 * t4.x, s1 * t3.y + s2 * t4.y);
    float2 b2 = make_float2(s2 * t3.x - s1 * t4.x, s2 * t3.y - s1 * t4.y);
    x[0] = make_float2(x0.x + t1.x + t2.x, x0.y + t1.y + t2.y);
    float2 ib1 = cmuli<DIR>(b1);
    float2 ib2 = cmuli<DIR>(b2);
    x[1] = cadd(a1, ib1);
    x[4] = csub(a1, ib1);
    x[2] = cadd(a2, ib2);
    x[3] = csub(a2, ib2);
}

// 10-point DFT = 2x5 CT, stride-S register access.
template <int DIR, int S>
__device__ __forceinline__ void dft10s(float2* x) {
    const float C36 = 0.80901699437494742f;
    const float S36 = 0.58778525229247313f;
    const float C72 = 0.30901699437494742f;
    const float S72 = 0.95105651629515357f;
    const float D = (float)DIR;
    float2 a[5], c[5];
#pragma unroll
    for (int k = 0; k < 5; k++) {
        a[k] = cadd(x[k * S], x[(k + 5) * S]);
        c[k] = csub(x[k * S], x[(k + 5) * S]);
    }
    c[1] = cmulc(c[1], C36, D * S36);
    c[2] = cmulc(c[2], C72, D * S72);
    c[3] = cmulc(c[3], -C72, D * S72);
    c[4] = cmulc(c[4], -C36, D * S36);
    dft5<DIR>(a);
    dft5<DIR>(c);
    x[0 * S] = a[0]; x[2 * S] = a[1]; x[4 * S] = a[2]; x[6 * S] = a[3]; x[8 * S] = a[4];
    x[1 * S] = c[0]; x[3 * S] = c[1]; x[5 * S] = c[2]; x[7 * S] = c[3]; x[9 * S] = c[4];
}

// 16-point DFT = 4x4 CT, stride-S register access.
template <int DIR, int S>
__device__ __forceinline__ void dft16s(float2* x) {
    const float C1 = 0.92387953251128674f;
    const float S1 = 0.38268343236508978f;
    const float C2 = 0.70710678118654752f;
    const float D = (float)DIR;
    float2 y[16];
#pragma unroll
    for (int n2 = 0; n2 < 4; n2++) {
        float2 t[4] = {x[n2 * S], x[(n2 + 4) * S], x[(n2 + 8) * S], x[(n2 + 12) * S]};
        dft4<DIR>(t);
        if (n2 == 1) {
            t[1] = cmulc(t[1], C1, D * S1);
            t[2] = cmulc(t[2], C2, D * C2);
            t[3] = cmulc(t[3], S1, D * C1);
        } else if (n2 == 2) {
            t[1] = cmulc(t[1], C2, D * C2);
            t[2] = cmuli<DIR>(t[2]);
            t[3] = cmulc(t[3], -C2, D * C2);
        } else if (n2 == 3) {
            t[1] = cmulc(t[1], S1, D * C1);
            t[2] = cmulc(t[2], -C2, D * C2);
            t[3] = cmulc(t[3], -C1, -D * S1);
        }
        y[0 + n2] = t[0]; y[4 + n2] = t[1]; y[8 + n2] = t[2]; y[12 + n2] = t[3];
    }
#pragma unroll
    for (int k1 = 0; k1 < 4; k1++) {
        float2 t[4] = {y[k1 * 4 + 0], y[k1 * 4 + 1], y[k1 * 4 + 2], y[k1 * 4 + 3]};
        dft4<DIR>(t);
        x[(k1 + 0) * S] = t[0]; x[(k1 + 4) * S] = t[1];
        x[(k1 + 8) * S] = t[2]; x[(k1 + 12) * S] = t[3];
    }
}

// Twiddle application: odd/even accumulator chains stepping by w^2.
template <int S>
__device__ __forceinline__ void apply_tw10_chain(float2* x, float2 w1) {
    float2 w2 = cmul(w1, w1);
    float2 wo = w1, we = w2;
    x[1 * S] = cmul(x[1 * S], wo);
    x[2 * S] = cmul(x[2 * S], we);
#pragma unroll
    for (int j = 3; j < 10; j += 2) {
        wo = cmul(wo, w2); x[j * S] = cmul(x[j * S], wo);
        if (j + 1 < 10) { we = cmul(we, w2); x[(j + 1) * S] = cmul(x[(j + 1) * S], we); }
    }
}

template <int S>
__device__ __forceinline__ void apply_tw16_chain(float2* x, float2 w1) {
    float2 w2 = cmul(w1, w1);
    float2 wo = w1, we = w2;
    x[1 * S] = cmul(x[1 * S], wo);
    x[2 * S] = cmul(x[2 * S], we);
#pragma unroll
    for (int j = 3; j < 16; j += 2) {
        wo = cmul(wo, w2); x[j * S] = cmul(x[j * S], wo);
        if (j + 1 < 16) { we = cmul(we, w2); x[(j + 1) * S] = cmul(x[(j + 1) * S], we); }
    }
}

// Forward radix-16 stage (NS=16000, m=1000), DIF, paired via float4.
// Twiddle pair LDG issued BEFORE the smem loads so its latency overlaps the DFTs.
__device__ __forceinline__ void stage16_fwd(float2* sm, int tid) {
    if (tid >= 500) return;
    int n2 = 2 * tid;
    float4 wv = *(const float4*)&g_tw[n2];   // prefetch (global, coalesced)
    float2 X[32];   // even slots: butterfly A (n2), odd: butterfly B (n2+1)
#pragma unroll
    for (int j = 0; j < 16; j++) {
        float4 t = *(const float4*)&sm[PHI(n2 + j * 1000)];
        X[2 * j]     = make_float2(t.x, t.y);
        X[2 * j + 1] = make_float2(t.z, t.w);
    }
    dft16s<-1, 2>(X);
    dft16s<-1, 2>(X + 1);
    apply_tw16_chain<2>(X, make_float2(wv.x, wv.y));
    apply_tw16_chain<2>(X + 1, make_float2(wv.z, wv.w));
#pragma unroll
    for (int j = 0; j < 16; j++) {
        *(float4*)&sm[PHI(n2 + j * 1000)] =
            make_float4(X[2 * j].x, X[2 * j].y, X[2 * j + 1].x, X[2 * j + 1].y);
    }
}

// Forward radix-10 stage, two adjacent butterflies per thread; 800 tasks = BT.
template <int NS>
__device__ __forceinline__ void stage10_paired(float2* sm, int tid, const float2* __restrict__ tab) {
    constexpr int m = NS / 10;
    constexpr int halfm = m / 2;
    int blk = tid / halfm;
    int h = tid - blk * halfm;
    int n2 = 2 * h;
    int base = blk * NS + n2;
    float4 wv = *(const float4*)&tab[n2];    // prefetch
    float2 X[20];
#pragma unroll
    for (int j = 0; j < 10; j++) {
        float4 t = *(const float4*)&sm[PHI(base + j * m)];
        X[2 * j]     = make_float2(t.x, t.y);
        X[2 * j + 1] = make_float2(t.z, t.w);
    }
    dft10s<-1, 2>(X);
    apply_tw10_chain<2>(X, make_float2(wv.x, wv.y));
    dft10s<-1, 2>(X + 1);
    apply_tw10_chain<2>(X + 1, make_float2(wv.z, wv.w));
#pragma unroll
    for (int j = 0; j < 10; j++) {
        *(float4*)&sm[PHI(base + j * m)] =
            make_float4(X[2 * j].x, X[2 * j].y, X[2 * j + 1].x, X[2 * j + 1].y);
    }
}

// Inverse (DIT) stage on the 8000-point array; w1 from pre-conjugated coalesced table.
template <int R, int NS, bool TO_GMEM>
__device__ __forceinline__ void stage8_inv(float2* s8, int tid, float2* __restrict__ gout2,
                                           const float2* __restrict__ tab) {
    constexpr int m = NS / R;
    constexpr int nb = NH / R;
    for (int u = tid; u < nb; u += BT) {
        int blk = u / m;
        int n2 = u - blk * m;
        int base = blk * NS + n2;
        float2 w1 = tab[n2];                 // prefetch before smem loads
        float2 x[R];
#pragma unroll
        for (int j = 0; j < R; j++) x[j] = s8[PHI8(base + j * m)];
        if constexpr (R == 16) {
            apply_tw16_chain<1>(x, w1);
            dft16s<1, 1>(x);
        } else {
            apply_tw10_chain<1>(x, w1);
            dft10s<1, 1>(x);
        }
#pragma unroll
        for (int j = 0; j < R; j++) {
            if constexpr (TO_GMEM) gout2[base + j * m] = x[j];   // c[n] -> (z[2n], z[2n+1])
            else s8[PHI8(base + j * m)] = x[j];
        }
    }
}

__device__ __forceinline__ void pw(float2& A, float2& C, float scale) {
    float2 a = A, c = C;
    float2 Fi = make_float2(a.x + c.x, a.y - c.y);
    float2 Fs = make_float2(a.y + c.y, -(a.x - c.x));
    float2 Z = cmul(Fi, Fs);
    Z.x *= scale; Z.y *= scale;
    A = Z;
    C = make_float2(Z.x, -Z.y);
}

// Pack Z-block (10 values, f = f0+1600t) into 5 C values of the 8000-domain,
// then first inverse stage (radix-5), store at s8[PHI8(5b + j)].
__device__ __forceinline__ void pack_inv5_store(const float2* x, float2 w0,
                                                float2* s8, int b) {
    const float RC[5] = {1.f, 0.80901699437494742f, 0.30901699437494742f,
                         -0.30901699437494742f, -0.80901699437494742f};
    const float RS[5] = {0.f, 0.58778525229247313f, 0.95105651629515357f,
                         0.95105651629515357f, 0.58778525229247313f};
    float2 C[5];
#pragma unroll
    for (int t = 0; t < 5; t++) {
        float2 S = cadd(x[t], x[t + 5]);
        float2 Dd = csub(x[t], x[t + 5]);
        float2 wt = (t == 0) ? w0 : cmul(w0, make_float2(RC[t], RS[t]));
        C[t] = cadd(S, cmuli<1>(cmul(wt, Dd)));
    }
    dft5<1>(C);
    int base = PHI8(5 * b);   // 5b..5b+4 never cross a 50-group
#pragma unroll
    for (int j = 0; j < 5; j++) s8[base + j] = C[j];
}

// Fused middle: forward radix-10 (m=1) + Hermitian pointwise + pack + inverse radix-5.
__device__ __forceinline__ void fused_mid(float2* sm, float2* s8, int tid) {
    const float scale = 0.25f / (float)NFFT;
    int fa, fb;
    if (tid < 799) { fa = tid + 1; fb = 1600 - fa; }
    else           { fa = 0;       fb = 800; }
    int b  = block_of(fa);
    int b2 = block_of(fb);
    int pa = PHI(10 * b);
    int pb = PHI(10 * b2);
    float2 ta = g_tw[fa]; ta.y = -ta.y;   // prefetch; e^{+2pi i fa/16000}
    float2 tb = g_tw[fb]; tb.y = -tb.y;
    float2 xa[10], xb[10];
#pragma unroll
    for (int k = 0; k < 5; k++) {
        float4 t = *(const float4*)&sm[pa + 2 * k];
        xa[2 * k] = make_float2(t.x, t.y); xa[2 * k + 1] = make_float2(t.z, t.w);
        float4 s = *(const float4*)&sm[pb + 2 * k];
        xb[2 * k] = make_float2(s.x, s.y); xb[2 * k + 1] = make_float2(s.z, s.w);
    }
    dft10s<-1, 1>(xa);
    dft10s<-1, 1>(xb);
    if (tid < 799) {
#pragma unroll
        for (int t = 0; t < 10; t++) pw(xa[t], xb[9 - t], scale);
    } else {
        pw(xa[0], xa[0], scale);
        pw(xa[5], xa[5], scale);
        pw(xa[1], xa[9], scale);
        pw(xa[2], xa[8], scale);
        pw(xa[3], xa[7], scale);
        pw(xa[4], xa[6], scale);
        pw(xb[0], xb[9], scale);
        pw(xb[1], xb[8], scale);
        pw(xb[2], xb[7], scale);
        pw(xb[3], xb[6], scale);
        pw(xb[4], xb[5], scale);
    }
    pack_inv5_store(xa, ta, s8, b);
    pack_inv5_store(xb, tb, s8, b2);
}

__global__ void __launch_bounds__(BT) mcb_main_kernel(
    const float* __restrict__ img, const float* __restrict__ seq,
    const int* __restrict__ hv, const float* __restrict__ sv,
    float* __restrict__ out, int d) {
    extern __shared__ float2 sm[];
    float2* s8 = sm + SMPAD;
    const int b = blockIdx.x;
    const int tid = threadIdx.x;

    float4* sm4 = (float4*)sm;
    for (int i = tid; i < SMPAD / 2; i += BT) sm4[i] = make_float4(0.f, 0.f, 0.f, 0.f);
    __syncthreads();

    // vectorized scatter: FOUR features per iteration (int4/float4 loads;
    // row bases are 16B-aligned: row stride = d floats, d % 4 == 0).
    {
        const int Q = d >> 2;   // feature quads (512 for d=2048 -> single pass)
        const int4*   hv4 = (const int4*)hv;
        const float4* sv4 = (const float4*)sv;
        const float4* im4 = (const float4*)(img + (size_t)b * d);
        const float4* sq4 = (const float4*)(seq + (size_t)b * d);
        for (int i = tid; i < Q; i += BT) {
            int4   h4 = hv4[i];
            float4 s4 = sv4[i];
            float4 a4 = im4[i];
            float4 q4 = sq4[i];
            int h0 = PHI(h4.x), h1 = PHI(h4.y), h2 = PHI(h4.z), h3 = PHI(h4.w);
            atomicAdd(&sm[h0].x, a4.x * s4.x);
            atomicAdd(&sm[h0].y, q4.x * s4.x);
            atomicAdd(&sm[h1].x, a4.y * s4.y);
            atomicAdd(&sm[h1].y, q4.y * s4.y);
            atomicAdd(&sm[h2].x, a4.z * s4.z);
            atomicAdd(&sm[h2].y, q4.z * s4.z);
            atomicAdd(&sm[h3].x, a4.w * s4.w);
            atomicAdd(&sm[h3].y, q4.w * s4.w);
        }
    }
    __syncthreads();

    float2* orow2 = (float2*)(out + (size_t)b * NFFT);

    // forward 16000: 16 (paired), 10, 10 | fused(10 + pointwise + pack + inv5)
    stage16_fwd(sm, tid);                        __syncthreads();
    stage10_paired<1000>(sm, tid, g_twf1000);    __syncthreads();
    stage10_paired<100>(sm, tid, g_twf100);      __syncthreads();
    fused_mid(sm, s8, tid);                      __syncthreads();
    // inverse 8000: 10 (m=5), 10 (m=50), 16 (m=500) -> gmem float2
    stage8_inv<10, 50, false>(s8, tid, orow2, g_twi50);     __syncthreads();
    stage8_inv<10, 500, false>(s8, tid, orow2, g_twi500);   __syncthreads();
    stage8_inv<16, 8000, true>(s8, tid, orow2, g_twi8000);
}

extern "C" void kernel_launch(void* const* d_in, const int* in_sizes, int n_in,
                              void* d_out, int out_size) {
    const float* img = (const float*)d_in[0];
    const float* seq = (const float*)d_in[1];
    const int* hv = (const int*)d_in[2];
    const float* sv = (const float*)d_in[3];
    float* out = (float*)d_out;

    int d = in_sizes[2];
    int B = in_sizes[0] / d;

    static_assert(NFFT == 16000 && NH == 8000, "plan assumes N=16000");

    cudaFuncSetAttribute(mcb_main_kernel, cudaFuncAttributeMaxDynamicSharedMemorySize,
                         SMTOTAL);

    init_tables_kernel<<<(N_INIT + 255) / 256, 256>>>();
    mcb_main_kernel<<<B, BT, SMTOTAL>>>(img, seq, hv, sv, out, d);
}